// round 1
// baseline (speedup 1.0000x reference)
#include <cuda_runtime.h>
#include <math.h>

// Problem constants
#define NN 10000
#define EE 160000

// ---------------- device scratch (no allocs allowed) ----------------
__device__ float g_proj1[NN * 256];         // [N,2,128]
__device__ float g_ssrc1[NN * 2];
__device__ float g_strg1[NN * 2];
__device__ float g_e1[EE * 2];              // e then ex (in place)
__device__ unsigned g_max1;
__device__ float g_den1[NN * 2];
__device__ float g_agg1[NN * 256];
__device__ float g_h[NN * 512];
__device__ float g_proj2[NN * 512];         // [N,4,128]
__device__ float g_ssrc2[NN * 4];
__device__ float g_strg2[NN * 4];
__device__ float g_e2[EE * 4];
__device__ unsigned g_max2;
__device__ float g_den2[NN * 4];
__device__ float g_agg2[NN * 512];
__device__ float g_out2[NN * 128];
__device__ float g_wac[128 * 1024];         // Wi[0:128]+Wi[256:384]
__device__ float g_wad[128 * 1024];         // Wi[0:128]+Wi[384:512]
__device__ float g_P[NN * 1024];
__device__ float g_Q[NN * 1024];

// ordered-uint encoding of float for atomicMax
__device__ __forceinline__ unsigned fenc(float f) {
    unsigned u = __float_as_uint(f);
    return (u & 0x80000000u) ? ~u : (u | 0x80000000u);
}
__device__ __forceinline__ float fdec(unsigned u) {
    return (u & 0x80000000u) ? __uint_as_float(u & 0x7FFFFFFFu) : __uint_as_float(~u);
}
__device__ __forceinline__ float eluf(float v) { return v > 0.f ? v : expm1f(v); }

// ---------------- init: zero accumulators, reset maxes ----------------
__global__ void k_init() {
    int i = blockIdx.x * blockDim.x + threadIdx.x;
    int stride = gridDim.x * blockDim.x;
    for (int j = i; j < NN * 256; j += stride) g_agg1[j] = 0.f;
    for (int j = i; j < NN * 512; j += stride) g_agg2[j] = 0.f;
    for (int j = i; j < NN * 2; j += stride) g_den1[j] = 0.f;
    for (int j = i; j < NN * 4; j += stride) g_den2[j] = 0.f;
    if (i == 0) { g_max1 = 0u; g_max2 = 0u; }  // 0 < any real float encoding
}

// ---------------- per-node-row GEMM: out[n, :COLS] = X[n, :K] @ W ----------------
template <int K, int COLS, int THREADS>
__global__ void k_gemm_node(const float* __restrict__ X, const float* __restrict__ W,
                            float* __restrict__ out) {
    constexpr int V = COLS / THREADS;
    static_assert(V == 2 || V == 4, "V");
    __shared__ float xs[K];
    int n = blockIdx.x;
    for (int k = threadIdx.x; k < K; k += THREADS) xs[k] = X[(size_t)n * K + k];
    __syncthreads();
    int c0 = threadIdx.x * V;
    if (V == 4) {
        const float4* wp = (const float4*)(W + c0);
        float4 a = {0.f, 0.f, 0.f, 0.f};
#pragma unroll 4
        for (int k = 0; k < K; k++) {
            float x = xs[k];
            float4 w = wp[(size_t)k * (COLS / 4)];
            a.x += x * w.x; a.y += x * w.y; a.z += x * w.z; a.w += x * w.w;
        }
        *(float4*)(out + (size_t)n * COLS + c0) = a;
    } else {
        const float2* wp = (const float2*)(W + c0);
        float2 a = {0.f, 0.f};
#pragma unroll 4
        for (int k = 0; k < K; k++) {
            float x = xs[k];
            float2 w = wp[(size_t)k * (COLS / 2)];
            a.x += x * w.x; a.y += x * w.y;
        }
        *(float2*)(out + (size_t)n * COLS + c0) = a;
    }
}

// ---------------- attention score projections s_src, s_trg ----------------
template <int H>
__global__ void k_scores(const float* __restrict__ proj, const float* __restrict__ asrc,
                         const float* __restrict__ atrg, float* __restrict__ ssrc,
                         float* __restrict__ strg) {
    int n = blockIdx.x;
    int h = threadIdx.x >> 5, lane = threadIdx.x & 31;
    float4 p = *(const float4*)(proj + ((size_t)n * H + h) * 128 + lane * 4);
    float4 a = *(const float4*)(asrc + h * 128 + lane * 4);
    float4 b = *(const float4*)(atrg + h * 128 + lane * 4);
    float ps = p.x * a.x + p.y * a.y + p.z * a.z + p.w * a.w;
    float pt = p.x * b.x + p.y * b.y + p.z * b.z + p.w * b.w;
#pragma unroll
    for (int o = 16; o > 0; o >>= 1) {
        ps += __shfl_down_sync(0xffffffffu, ps, o);
        pt += __shfl_down_sync(0xffffffffu, pt, o);
    }
    if (lane == 0) { ssrc[n * H + h] = ps; strg[n * H + h] = pt; }
}

// ---------------- edge pass 1: leaky-relu logits + global max ----------------
template <int H>
__global__ void k_edge_logits(const int* __restrict__ ei, const float* __restrict__ ss,
                              const float* __restrict__ st, float* __restrict__ eb,
                              unsigned* __restrict__ gmax) {
    int i = blockIdx.x * blockDim.x + threadIdx.x;
    unsigned lm = 0u;
    if (i < EE) {
        int s = ei[i], t = ei[EE + i];
#pragma unroll
        for (int h = 0; h < H; h++) {
            float v = ss[s * H + h] + st[t * H + h];
            v = v > 0.f ? v : 0.2f * v;
            eb[(size_t)i * H + h] = v;
            unsigned e = fenc(v);
            lm = lm > e ? lm : e;
        }
    }
#pragma unroll
    for (int o = 16; o > 0; o >>= 1) {
        unsigned other = __shfl_xor_sync(0xffffffffu, lm, o);
        lm = lm > other ? lm : other;
    }
    __shared__ unsigned wm[8];
    if ((threadIdx.x & 31) == 0) wm[threadIdx.x >> 5] = lm;
    __syncthreads();
    if (threadIdx.x == 0) {
        unsigned m = wm[0];
#pragma unroll
        for (int w = 1; w < 8; w++) m = m > wm[w] ? m : wm[w];
        atomicMax(gmax, m);
    }
}

// ---------------- edge pass 2: exp(e - max), denom segment-sum ----------------
template <int H>
__global__ void k_edge_exp(const int* __restrict__ ei, float* __restrict__ eb,
                           const unsigned* __restrict__ gmax, float* __restrict__ den) {
    int i = blockIdx.x * blockDim.x + threadIdx.x;
    if (i >= EE) return;
    float mx = fdec(*gmax);
    int t = ei[EE + i];
#pragma unroll
    for (int h = 0; h < H; h++) {
        float ex = expf(eb[(size_t)i * H + h] - mx);
        eb[(size_t)i * H + h] = ex;
        atomicAdd(&den[t * H + h], ex);
    }
}

// ---------------- edge pass 3: scatter attention-weighted messages ----------------
template <int H>
__global__ void k_edge_agg(const int* __restrict__ ei, const float* __restrict__ eb,
                           const float* __restrict__ den, const float* __restrict__ proj,
                           float* __restrict__ agg) {
    int g = blockIdx.x * blockDim.x + threadIdx.x;
    int i = g >> 5, lane = g & 31;
    if (i >= EE) return;
    int s = ei[i], t = ei[EE + i];
#pragma unroll
    for (int h = 0; h < H; h++) {
        float att = eb[(size_t)i * H + h] / (den[t * H + h] + 1e-16f);
        float4 p = *(const float4*)(proj + ((size_t)s * H + h) * 128 + lane * 4);
        float* d = agg + ((size_t)t * H + h) * 128 + lane * 4;
        atomicAdd(d + 0, p.x * att);
        atomicAdd(d + 1, p.y * att);
        atomicAdd(d + 2, p.z * att);
        atomicAdd(d + 3, p.w * att);
    }
}

// ---------------- layer-1 finalize: concat residual, +b1, elu ----------------
__global__ void k_finalize1(const float* __restrict__ local_emb, const float* __restrict__ b1,
                            const float* __restrict__ agg, float* __restrict__ hbuf) {
    int n = blockIdx.x, c = threadIdx.x;  // 512 threads
    int h = c >> 8, j = c & 255;
    float v = (j < 128) ? agg[(size_t)n * 256 + h * 128 + j]
                        : local_emb[(size_t)n * 128 + (j - 128)];
    v += b1[c];
    hbuf[(size_t)n * 512 + c] = eluf(v);
}

// ---------------- layer-2 finalize: mean over 4 heads, +b2, elu ----------------
__global__ void k_finalize2(const float* __restrict__ b2, const float* __restrict__ agg,
                            float* __restrict__ out2) {
    int n = blockIdx.x, f = threadIdx.x;  // 128 threads
    const float* a = agg + (size_t)n * 512;
    float v = 0.25f * (a[f] + a[128 + f] + a[256 + f] + a[384 + f]) + b2[f];
    out2[(size_t)n * 128 + f] = eluf(v);
}

// ---------------- MLP weight factorization: Wi_a+Wi_c, Wi_a+Wi_d ----------------
__global__ void k_wprep(const float* __restrict__ Wi, float* __restrict__ wac,
                        float* __restrict__ wad) {
    int i = blockIdx.x * blockDim.x + threadIdx.x;
    if (i >= 128 * 1024) return;
    int f = i >> 10, j = i & 1023;
    float a = Wi[i];  // rows 0..127
    wac[i] = a + Wi[(size_t)(256 + f) * 1024 + j];
    wad[i] = a + Wi[(size_t)(384 + f) * 1024 + j];
}

// ---------------- fused per-edge MLP (factorized layer 1) ----------------
// fused[e,j] = relu(P[src][j] + Q[trg][j] + (e1*e2) @ Wi_b[:,j] + bi[j])
// hdn[e,o]   = relu(fused[e,:] @ Wf1[:,o] + bf1[o])
// out[e]     = sigmoid(hdn[e,:] @ Wf2 + bf2)
#define TE 32
__global__ __launch_bounds__(256, 2) void k_edge_mlp(
    const int* __restrict__ ei, const float* __restrict__ out2,
    const float* __restrict__ P, const float* __restrict__ Q,
    const float* __restrict__ Wi, const float* __restrict__ bi,
    const float* __restrict__ Wf1, const float* __restrict__ bf1,
    const float* __restrict__ Wf2, const float* __restrict__ bf2,
    float* __restrict__ outp) {
    __shared__ float msh[TE][128];  // e1*e2
    __shared__ float ch[TE][128];   // fused chunk, post-relu
    __shared__ int ssrc[TE], strg[TE];
    int tid = threadIdx.x, ty = tid >> 5, tx = tid & 31;
    int e0 = blockIdx.x * TE;
    if (tid < TE) { ssrc[tid] = ei[e0 + tid]; strg[tid] = ei[EE + e0 + tid]; }
    __syncthreads();
    // build m = e1*e2 in smem (float4 vectorized)
    for (int idx = tid; idx < TE * 32; idx += 256) {
        int e = idx >> 5, f4 = idx & 31;
        float4 a = *(const float4*)(out2 + (size_t)ssrc[e] * 128 + f4 * 4);
        float4 b = *(const float4*)(out2 + (size_t)strg[e] * 128 + f4 * 4);
        float4 m;
        m.x = a.x * b.x; m.y = a.y * b.y; m.z = a.z * b.z; m.w = a.w * b.w;
        *(float4*)(&msh[e][f4 * 4]) = m;
    }
    __syncthreads();

    const int eA = ty * 4;
    int s[4], t[4];
#pragma unroll
    for (int e = 0; e < 4; e++) { s[e] = ssrc[eA + e]; t[e] = strg[eA + e]; }

    // hdn accumulators: [edge][q][r], column o = q*128 + tx*4 + r
    float hacc[4][4][4];
#pragma unroll
    for (int a = 0; a < 4; a++)
#pragma unroll
        for (int b = 0; b < 4; b++)
#pragma unroll
            for (int c = 0; c < 4; c++) hacc[a][b][c] = 0.f;

    for (int c = 0; c < 8; c++) {
        int jb = c << 7;
        // GEMM1: fused chunk cols j = jb + tx*4 + r
        float4 acc[4];
        float4 bv = *(const float4*)(bi + jb + tx * 4);
#pragma unroll
        for (int e = 0; e < 4; e++) {
            float4 pv = *(const float4*)(P + (size_t)s[e] * 1024 + jb + tx * 4);
            float4 qv = *(const float4*)(Q + (size_t)t[e] * 1024 + jb + tx * 4);
            acc[e].x = pv.x + qv.x + bv.x;
            acc[e].y = pv.y + qv.y + bv.y;
            acc[e].z = pv.z + qv.z + bv.z;
            acc[e].w = pv.w + qv.w + bv.w;
        }
        const float* wb = Wi + (size_t)128 * 1024 + jb + tx * 4;
#pragma unroll 4
        for (int k = 0; k < 128; k++) {
            float4 w = *(const float4*)(wb + (size_t)k * 1024);
#pragma unroll
            for (int e = 0; e < 4; e++) {
                float mv = msh[eA + e][k];
                acc[e].x += mv * w.x; acc[e].y += mv * w.y;
                acc[e].z += mv * w.z; acc[e].w += mv * w.w;
            }
        }
        __syncthreads();  // previous GEMM2 reads of ch complete
#pragma unroll
        for (int e = 0; e < 4; e++) {
            float4 rv;
            rv.x = fmaxf(acc[e].x, 0.f); rv.y = fmaxf(acc[e].y, 0.f);
            rv.z = fmaxf(acc[e].z, 0.f); rv.w = fmaxf(acc[e].w, 0.f);
            *(float4*)(&ch[eA + e][tx * 4]) = rv;
        }
        __syncthreads();
        // GEMM2 partial: hacc += ch @ Wf1[jb:jb+128, :]
        const float* wf = Wf1 + (size_t)jb * 512 + tx * 4;
#pragma unroll 2
        for (int j = 0; j < 128; j++) {
            float cv[4];
#pragma unroll
            for (int e = 0; e < 4; e++) cv[e] = ch[eA + e][j];
            const float* wr = wf + (size_t)j * 512;
#pragma unroll
            for (int q = 0; q < 4; q++) {
                float4 w = *(const float4*)(wr + q * 128);
#pragma unroll
                for (int e = 0; e < 4; e++) {
                    hacc[e][q][0] += cv[e] * w.x;
                    hacc[e][q][1] += cv[e] * w.y;
                    hacc[e][q][2] += cv[e] * w.z;
                    hacc[e][q][3] += cv[e] * w.w;
                }
            }
        }
    }
    // epilogue: relu(hdn + bf1) @ Wf2, warp-reduce, sigmoid
    float part[4] = {0.f, 0.f, 0.f, 0.f};
#pragma unroll
    for (int q = 0; q < 4; q++) {
        int o = q * 128 + tx * 4;
        float4 b = *(const float4*)(bf1 + o);
        float4 w = *(const float4*)(Wf2 + o);
#pragma unroll
        for (int e = 0; e < 4; e++) {
            part[e] += fmaxf(hacc[e][q][0] + b.x, 0.f) * w.x +
                       fmaxf(hacc[e][q][1] + b.y, 0.f) * w.y +
                       fmaxf(hacc[e][q][2] + b.z, 0.f) * w.z +
                       fmaxf(hacc[e][q][3] + b.w, 0.f) * w.w;
        }
    }
#pragma unroll
    for (int o = 16; o > 0; o >>= 1) {
#pragma unroll
        for (int e = 0; e < 4; e++) part[e] += __shfl_down_sync(0xffffffffu, part[e], o);
    }
    if (tx == 0) {
        float b2v = bf2[0];
#pragma unroll
        for (int e = 0; e < 4; e++) {
            float lg = part[e] + b2v;
            outp[e0 + eA + e] = 1.f / (1.f + expf(-lg));
        }
    }
}

// ---------------- launch ----------------
extern "C" void kernel_launch(void* const* d_in, const int* in_sizes, int n_in,
                              void* d_out, int out_size) {
    const float* x = (const float*)d_in[0];
    const int* ei = (const int*)d_in[1];
    const float* local_emb = (const float*)d_in[2];
    const float* W1 = (const float*)d_in[3];
    const float* a_src1 = (const float*)d_in[4];
    const float* a_trg1 = (const float*)d_in[5];
    const float* b1 = (const float*)d_in[6];
    const float* W2 = (const float*)d_in[7];
    const float* a_src2 = (const float*)d_in[8];
    const float* a_trg2 = (const float*)d_in[9];
    const float* b2 = (const float*)d_in[10];
    const float* Wi = (const float*)d_in[11];
    const float* bi = (const float*)d_in[12];
    const float* Wf1 = (const float*)d_in[13];
    const float* bf1 = (const float*)d_in[14];
    const float* Wf2 = (const float*)d_in[15];
    const float* bf2 = (const float*)d_in[16];
    float* outp = (float*)d_out;

    void* tmp;
    float *p_proj1, *p_ssrc1, *p_strg1, *p_e1, *p_den1, *p_agg1, *p_h;
    float *p_proj2, *p_ssrc2, *p_strg2, *p_e2, *p_den2, *p_agg2, *p_out2;
    float *p_wac, *p_wad, *p_P, *p_Q;
    unsigned *p_max1, *p_max2;
#define SYM(p, s) cudaGetSymbolAddress(&tmp, s); p = (decltype(p))tmp;
    SYM(p_proj1, g_proj1) SYM(p_ssrc1, g_ssrc1) SYM(p_strg1, g_strg1)
    SYM(p_e1, g_e1) SYM(p_den1, g_den1) SYM(p_agg1, g_agg1) SYM(p_h, g_h)
    SYM(p_proj2, g_proj2) SYM(p_ssrc2, g_ssrc2) SYM(p_strg2, g_strg2)
    SYM(p_e2, g_e2) SYM(p_den2, g_den2) SYM(p_agg2, g_agg2) SYM(p_out2, g_out2)
    SYM(p_wac, g_wac) SYM(p_wad, g_wad) SYM(p_P, g_P) SYM(p_Q, g_Q)
    SYM(p_max1, g_max1) SYM(p_max2, g_max2)
#undef SYM

    const int EB = (EE + 255) / 256;  // 625

    k_init<<<256, 256>>>();

    // ---- GAT layer 1 ----
    k_gemm_node<128, 256, 128><<<NN, 128>>>(x, W1, p_proj1);
    k_scores<2><<<NN, 64>>>(p_proj1, a_src1, a_trg1, p_ssrc1, p_strg1);
    k_edge_logits<2><<<EB, 256>>>(ei, p_ssrc1, p_strg1, p_e1, p_max1);
    k_edge_exp<2><<<EB, 256>>>(ei, p_e1, p_max1, p_den1);
    k_edge_agg<2><<<EE / 8, 256>>>(ei, p_e1, p_den1, p_proj1, p_agg1);
    k_finalize1<<<NN, 512>>>(local_emb, b1, p_agg1, p_h);

    // ---- GAT layer 2 ----
    k_gemm_node<512, 512, 128><<<NN, 128>>>(p_h, W2, p_proj2);
    k_scores<4><<<NN, 128>>>(p_proj2, a_src2, a_trg2, p_ssrc2, p_strg2);
    k_edge_logits<4><<<EB, 256>>>(ei, p_ssrc2, p_strg2, p_e2, p_max2);
    k_edge_exp<4><<<EB, 256>>>(ei, p_e2, p_max2, p_den2);
    k_edge_agg<4><<<EE / 8, 256>>>(ei, p_e2, p_den2, p_proj2, p_agg2);
    k_finalize2<<<NN, 128>>>(b2, p_agg2, p_out2);

    // ---- edge MLP (factorized first layer) ----
    k_wprep<<<512, 256>>>(Wi, p_wac, p_wad);
    k_gemm_node<128, 1024, 256><<<NN, 256>>>(p_out2, p_wac, p_P);
    k_gemm_node<128, 1024, 256><<<NN, 256>>>(p_out2, p_wad, p_Q);
    k_edge_mlp<<<EE / TE, 256>>>(ei, p_out2, p_P, p_Q, Wi, bi, Wf1, bf1, Wf2, bf2, outp);
}

// round 3
// speedup vs baseline: 1.7355x; 1.7355x over previous
#include <cuda_runtime.h>
#include <mma.h>
#include <math.h>

using namespace nvcuda;

#define NN 10000
#define EE 160000

// ---------------- device scratch ----------------
__device__ float g_proj1[NN * 256];
__device__ float g_ssrc1[NN * 2];
__device__ float g_strg1[NN * 2];
__device__ float g_e1[EE * 2];
__device__ unsigned g_max1;
__device__ float g_den1[NN * 2];
__device__ float g_agg1[NN * 256];
__device__ float g_h[NN * 512];
__device__ float g_proj2[NN * 512];
__device__ float g_ssrc2[NN * 4];
__device__ float g_strg2[NN * 4];
__device__ float g_e2[EE * 4];
__device__ unsigned g_max2;
__device__ float g_den2[NN * 4];
__device__ float g_agg2[NN * 512];
__device__ float g_out2[NN * 128];
__device__ float g_wac[128 * 1024];
__device__ float g_wad[128 * 1024];
__device__ float g_P[NN * 1024];
__device__ float g_Q[NN * 1024];

__device__ __forceinline__ unsigned fenc(float f) {
    unsigned u = __float_as_uint(f);
    return (u & 0x80000000u) ? ~u : (u | 0x80000000u);
}
__device__ __forceinline__ float fdec(unsigned u) {
    return (u & 0x80000000u) ? __uint_as_float(u & 0x7FFFFFFFu) : __uint_as_float(~u);
}
__device__ __forceinline__ float eluf(float v) { return v > 0.f ? v : expm1f(v); }

// ---------------- init ----------------
__global__ void k_init() {
    int i = blockIdx.x * blockDim.x + threadIdx.x;
    int stride = gridDim.x * blockDim.x;
    for (int j = i; j < NN * 256; j += stride) g_agg1[j] = 0.f;
    for (int j = i; j < NN * 512; j += stride) g_agg2[j] = 0.f;
    for (int j = i; j < NN * 2; j += stride) g_den1[j] = 0.f;
    for (int j = i; j < NN * 4; j += stride) g_den2[j] = 0.f;
    if (i == 0) { g_max1 = 0u; g_max2 = 0u; }
}

// ---------------- batched node GEMM: 16 nodes/block, weights reused 16x ----------------
template <int K, int COLS, int NB, int THREADS>
__global__ void k_gemm_nodes(const float* __restrict__ X, const float* __restrict__ W,
                             float* __restrict__ out) {
    __shared__ float xs[NB * K];
    int n0 = blockIdx.x * NB;
    for (int i = threadIdx.x; i < NB * K; i += THREADS) xs[i] = X[(size_t)n0 * K + i];
    __syncthreads();
    int c0 = threadIdx.x * 4;  // THREADS == COLS/4
    float4 acc[NB];
#pragma unroll
    for (int nb = 0; nb < NB; nb++) acc[nb] = make_float4(0.f, 0.f, 0.f, 0.f);
#pragma unroll 2
    for (int k = 0; k < K; k++) {
        float4 wv = *(const float4*)(W + (size_t)k * COLS + c0);
#pragma unroll
        for (int nb = 0; nb < NB; nb++) {
            float x = xs[nb * K + k];
            acc[nb].x += x * wv.x; acc[nb].y += x * wv.y;
            acc[nb].z += x * wv.z; acc[nb].w += x * wv.w;
        }
    }
#pragma unroll
    for (int nb = 0; nb < NB; nb++)
        *(float4*)(out + (size_t)(n0 + nb) * COLS + c0) = acc[nb];
}

// ---------------- attention score projections ----------------
template <int H>
__global__ void k_scores(const float* __restrict__ proj, const float* __restrict__ asrc,
                         const float* __restrict__ atrg, float* __restrict__ ssrc,
                         float* __restrict__ strg) {
    int n = blockIdx.x;
    int h = threadIdx.x >> 5, lane = threadIdx.x & 31;
    float4 p = *(const float4*)(proj + ((size_t)n * H + h) * 128 + lane * 4);
    float4 a = *(const float4*)(asrc + h * 128 + lane * 4);
    float4 b = *(const float4*)(atrg + h * 128 + lane * 4);
    float ps = p.x * a.x + p.y * a.y + p.z * a.z + p.w * a.w;
    float pt = p.x * b.x + p.y * b.y + p.z * b.z + p.w * b.w;
#pragma unroll
    for (int o = 16; o > 0; o >>= 1) {
        ps += __shfl_down_sync(0xffffffffu, ps, o);
        pt += __shfl_down_sync(0xffffffffu, pt, o);
    }
    if (lane == 0) { ssrc[n * H + h] = ps; strg[n * H + h] = pt; }
}

// ---------------- edge pass 1: logits + global max ----------------
template <int H>
__global__ void k_edge_logits(const int* __restrict__ ei, const float* __restrict__ ss,
                              const float* __restrict__ st, float* __restrict__ eb,
                              unsigned* __restrict__ gmax) {
    int i = blockIdx.x * blockDim.x + threadIdx.x;
    unsigned lm = 0u;
    if (i < EE) {
        int s = ei[i], t = ei[EE + i];
#pragma unroll
        for (int h = 0; h < H; h++) {
            float v = ss[s * H + h] + st[t * H + h];
            v = v > 0.f ? v : 0.2f * v;
            eb[(size_t)i * H + h] = v;
            unsigned e = fenc(v);
            lm = lm > e ? lm : e;
        }
    }
#pragma unroll
    for (int o = 16; o > 0; o >>= 1) {
        unsigned other = __shfl_xor_sync(0xffffffffu, lm, o);
        lm = lm > other ? lm : other;
    }
    __shared__ unsigned wm[8];
    if ((threadIdx.x & 31) == 0) wm[threadIdx.x >> 5] = lm;
    __syncthreads();
    if (threadIdx.x == 0) {
        unsigned m = wm[0];
#pragma unroll
        for (int w = 1; w < 8; w++) m = m > wm[w] ? m : wm[w];
        atomicMax(gmax, m);
    }
}

// ---------------- edge pass 2: exp + denom ----------------
template <int H>
__global__ void k_edge_exp(const int* __restrict__ ei, float* __restrict__ eb,
                           const unsigned* __restrict__ gmax, float* __restrict__ den) {
    int i = blockIdx.x * blockDim.x + threadIdx.x;
    if (i >= EE) return;
    float mx = fdec(*gmax);
    int t = ei[EE + i];
#pragma unroll
    for (int h = 0; h < H; h++) {
        float ex = expf(eb[(size_t)i * H + h] - mx);
        eb[(size_t)i * H + h] = ex;
        atomicAdd(&den[t * H + h], ex);
    }
}

// ---------------- edge pass 3: scatter messages ----------------
template <int H>
__global__ void k_edge_agg(const int* __restrict__ ei, const float* __restrict__ eb,
                           const float* __restrict__ den, const float* __restrict__ proj,
                           float* __restrict__ agg) {
    int g = blockIdx.x * blockDim.x + threadIdx.x;
    int i = g >> 5, lane = g & 31;
    if (i >= EE) return;
    int s = ei[i], t = ei[EE + i];
#pragma unroll
    for (int h = 0; h < H; h++) {
        float att = eb[(size_t)i * H + h] / (den[t * H + h] + 1e-16f);
        float4 p = *(const float4*)(proj + ((size_t)s * H + h) * 128 + lane * 4);
        float* d = agg + ((size_t)t * H + h) * 128 + lane * 4;
        atomicAdd(d + 0, p.x * att);
        atomicAdd(d + 1, p.y * att);
        atomicAdd(d + 2, p.z * att);
        atomicAdd(d + 3, p.w * att);
    }
}

__global__ void k_finalize1(const float* __restrict__ local_emb, const float* __restrict__ b1,
                            const float* __restrict__ agg, float* __restrict__ hbuf) {
    int n = blockIdx.x, c = threadIdx.x;
    int h = c >> 8, j = c & 255;
    float v = (j < 128) ? agg[(size_t)n * 256 + h * 128 + j]
                        : local_emb[(size_t)n * 128 + (j - 128)];
    v += b1[c];
    hbuf[(size_t)n * 512 + c] = eluf(v);
}

__global__ void k_finalize2(const float* __restrict__ b2, const float* __restrict__ agg,
                            float* __restrict__ out2) {
    int n = blockIdx.x, f = threadIdx.x;
    const float* a = agg + (size_t)n * 512;
    float v = 0.25f * (a[f] + a[128 + f] + a[256 + f] + a[384 + f]) + b2[f];
    out2[(size_t)n * 128 + f] = eluf(v);
}

__global__ void k_wprep(const float* __restrict__ Wi, float* __restrict__ wac,
                        float* __restrict__ wad) {
    int i = blockIdx.x * blockDim.x + threadIdx.x;
    if (i >= 128 * 1024) return;
    int f = i >> 10, j = i & 1023;
    float a = Wi[i];
    wac[i] = a + Wi[(size_t)(256 + f) * 1024 + j];
    wad[i] = a + Wi[(size_t)(384 + f) * 1024 + j];
}

// ---------------- fused per-edge MLP via tf32 tensor cores ----------------
// 64 edges/block, 8 warps. GEMM1: fused chunk = msh @ Wi_b[:,chunk]  (wmma tf32)
// then += P+Q+bi, relu. GEMM2: hdn accum (128 regs/thread frags) += chunk @ Wf1.
// Epilogue: relu(hdn+bf1) @ Wf2 -> sigmoid.
#define TE2 64
__global__ __launch_bounds__(256, 1) void k_edge_mlp2(
    const int* __restrict__ ei, const float* __restrict__ out2,
    const float* __restrict__ P, const float* __restrict__ Q,
    const float* __restrict__ Wi, const float* __restrict__ bi,
    const float* __restrict__ Wf1, const float* __restrict__ bf1,
    const float* __restrict__ Wf2, const float* __restrict__ bf2,
    float* __restrict__ outp) {
    extern __shared__ float smem[];
    float* msh = smem;                 // 64*128
    float* ch = msh + TE2 * 128;       // 64*128
    float* scr = ch + TE2 * 128;       // 8*256
    float* partial = scr + 8 * 256;    // 64
    float* bf1s = partial + 64;        // 512
    float* wf2s = bf1s + 512;          // 512
    int* sidx = (int*)(wf2s + 512);    // 64
    int* tidx = sidx + 64;             // 64

    int tid = threadIdx.x, w = tid >> 5, lane = tid & 31;
    int e0 = blockIdx.x * TE2;

    if (tid < TE2) {
        sidx[tid] = ei[e0 + tid];
        tidx[tid] = ei[EE + e0 + tid];
        partial[tid] = 0.f;
    }
    for (int i = tid; i < 512; i += 256) { bf1s[i] = bf1[i]; wf2s[i] = Wf2[i]; }
    __syncthreads();

    // msh = e1 * e2
    for (int idx = tid; idx < TE2 * 32; idx += 256) {
        int e = idx >> 5, j = (idx & 31) * 4;
        float4 a = *(const float4*)(out2 + (size_t)sidx[e] * 128 + j);
        float4 b = *(const float4*)(out2 + (size_t)tidx[e] * 128 + j);
        float4 m;
        m.x = a.x * b.x; m.y = a.y * b.y; m.z = a.z * b.z; m.w = a.w * b.w;
        *(float4*)(&msh[e * 128 + j]) = m;
    }

    wmma::fragment<wmma::accumulator, 16, 16, 8, float> hacc[4][4];
#pragma unroll
    for (int mt = 0; mt < 4; mt++)
#pragma unroll
        for (int nt = 0; nt < 4; nt++) wmma::fill_fragment(hacc[mt][nt], 0.f);
    __syncthreads();

    const int mt1 = w & 3;           // GEMM1 m-tile for this warp
    const int nb1 = (w >> 2) * 4;    // GEMM1 n-tile base (0 or 4)

    for (int c = 0; c < 8; c++) {
        int jb = c << 7;
        // ---- GEMM1: acc1 = msh @ Wi_b[:, jb:jb+128] ----
        wmma::fragment<wmma::accumulator, 16, 16, 8, float> acc1[4];
#pragma unroll
        for (int nt = 0; nt < 4; nt++) wmma::fill_fragment(acc1[nt], 0.f);
#pragma unroll 4
        for (int k = 0; k < 16; k++) {
            wmma::fragment<wmma::matrix_a, 16, 16, 8, wmma::precision::tf32, wmma::row_major> a;
            wmma::load_matrix_sync(a, msh + (mt1 * 16) * 128 + k * 8, 128);
#pragma unroll
            for (int i = 0; i < a.num_elements; i++) a.x[i] = wmma::__float_to_tf32(a.x[i]);
#pragma unroll
            for (int nt = 0; nt < 4; nt++) {
                wmma::fragment<wmma::matrix_b, 16, 16, 8, wmma::precision::tf32, wmma::row_major> b;
                wmma::load_matrix_sync(b, Wi + (size_t)(128 + k * 8) * 1024 + jb + (nb1 + nt) * 16, 1024);
#pragma unroll
                for (int i = 0; i < b.num_elements; i++) b.x[i] = wmma::__float_to_tf32(b.x[i]);
                wmma::mma_sync(acc1[nt], a, b, acc1[nt]);
            }
        }
        __syncthreads();  // previous chunk's GEMM2 reads of ch done
#pragma unroll
        for (int nt = 0; nt < 4; nt++)
            wmma::store_matrix_sync(ch + (mt1 * 16) * 128 + (nb1 + nt) * 16, acc1[nt], 128,
                                    wmma::mem_row_major);
        __syncthreads();
        // ---- elementwise: ch = relu(ch + P[s] + Q[t] + bi) ----
        for (int idx = tid; idx < TE2 * 32; idx += 256) {
            int e = idx >> 5, j = (idx & 31) * 4;
            float4 v = *(float4*)(&ch[e * 128 + j]);
            float4 p = *(const float4*)(P + (size_t)sidx[e] * 1024 + jb + j);
            float4 q = *(const float4*)(Q + (size_t)tidx[e] * 1024 + jb + j);
            float4 bv = *(const float4*)(bi + jb + j);
            v.x = fmaxf(v.x + p.x + q.x + bv.x, 0.f);
            v.y = fmaxf(v.y + p.y + q.y + bv.y, 0.f);
            v.z = fmaxf(v.z + p.z + q.z + bv.z, 0.f);
            v.w = fmaxf(v.w + p.w + q.w + bv.w, 0.f);
            *(float4*)(&ch[e * 128 + j]) = v;
        }
        __syncthreads();
        // ---- GEMM2: hacc += ch @ Wf1[jb:jb+128, :], warp n-range = w*64 ----
#pragma unroll 2
        for (int k = 0; k < 16; k++) {
            wmma::fragment<wmma::matrix_a, 16, 16, 8, wmma::precision::tf32, wmma::row_major> a[4];
#pragma unroll
            for (int mt = 0; mt < 4; mt++) {
                wmma::load_matrix_sync(a[mt], ch + (mt * 16) * 128 + k * 8, 128);
#pragma unroll
                for (int i = 0; i < a[mt].num_elements; i++)
                    a[mt].x[i] = wmma::__float_to_tf32(a[mt].x[i]);
            }
#pragma unroll
            for (int nt = 0; nt < 4; nt++) {
                wmma::fragment<wmma::matrix_b, 16, 16, 8, wmma::precision::tf32, wmma::row_major> b;
                wmma::load_matrix_sync(b, Wf1 + (size_t)(jb + k * 8) * 512 + w * 64 + nt * 16, 512);
#pragma unroll
                for (int i = 0; i < b.num_elements; i++) b.x[i] = wmma::__float_to_tf32(b.x[i]);
#pragma unroll
                for (int mt = 0; mt < 4; mt++)
                    wmma::mma_sync(hacc[mt][nt], a[mt], b, hacc[mt][nt]);
            }
        }
    }
    __syncthreads();

    // ---- epilogue: partial[m] += sum_n relu(hdn+bf1)*Wf2 ----
    float* myscr = scr + w * 256;
#pragma unroll
    for (int mt = 0; mt < 4; mt++) {
#pragma unroll
        for (int nt = 0; nt < 4; nt++) {
            wmma::store_matrix_sync(myscr, hacc[mt][nt], 16, wmma::mem_row_major);
            __syncwarp();
            int r = lane & 15, cc0 = (lane >> 4) * 8;
            int n0 = w * 64 + nt * 16 + cc0;
            float s = 0.f;
#pragma unroll
            for (int cc = 0; cc < 8; cc++) {
                float v = myscr[r * 16 + cc0 + cc];
                int n = n0 + cc;
                s += fmaxf(v + bf1s[n], 0.f) * wf2s[n];
            }
            atomicAdd(&partial[mt * 16 + r], s);
            __syncwarp();
        }
    }
    __syncthreads();
    if (tid < TE2) {
        float lg = partial[tid] + bf2[0];
        outp[e0 + tid] = 1.f / (1.f + expf(-lg));
    }
}

// ---------------- launch ----------------
extern "C" void kernel_launch(void* const* d_in, const int* in_sizes, int n_in,
                              void* d_out, int out_size) {
    const float* x = (const float*)d_in[0];
    const int* ei = (const int*)d_in[1];
    const float* local_emb = (const float*)d_in[2];
    const float* W1 = (const float*)d_in[3];
    const float* a_src1 = (const float*)d_in[4];
    const float* a_trg1 = (const float*)d_in[5];
    const float* b1 = (const float*)d_in[6];
    const float* W2 = (const float*)d_in[7];
    const float* a_src2 = (const float*)d_in[8];
    const float* a_trg2 = (const float*)d_in[9];
    const float* b2 = (const float*)d_in[10];
    const float* Wi = (const float*)d_in[11];
    const float* bi = (const float*)d_in[12];
    const float* Wf1 = (const float*)d_in[13];
    const float* bf1 = (const float*)d_in[14];
    const float* Wf2 = (const float*)d_in[15];
    const float* bf2 = (const float*)d_in[16];
    float* outp = (float*)d_out;

    void* tmp;
    float *p_proj1, *p_ssrc1, *p_strg1, *p_e1, *p_den1, *p_agg1, *p_h;
    float *p_proj2, *p_ssrc2, *p_strg2, *p_e2, *p_den2, *p_agg2, *p_out2;
    float *p_wac, *p_wad, *p_P, *p_Q;
    unsigned *p_max1, *p_max2;
#define SYM(p, s) cudaGetSymbolAddress(&tmp, s); p = (decltype(p))tmp;
    SYM(p_proj1, g_proj1) SYM(p_ssrc1, g_ssrc1) SYM(p_strg1, g_strg1)
    SYM(p_e1, g_e1) SYM(p_den1, g_den1) SYM(p_agg1, g_agg1) SYM(p_h, g_h)
    SYM(p_proj2, g_proj2) SYM(p_ssrc2, g_ssrc2) SYM(p_strg2, g_strg2)
    SYM(p_e2, g_e2) SYM(p_den2, g_den2) SYM(p_agg2, g_agg2) SYM(p_out2, g_out2)
    SYM(p_wac, g_wac) SYM(p_wad, g_wad) SYM(p_P, g_P) SYM(p_Q, g_Q)
    SYM(p_max1, g_max1) SYM(p_max2, g_max2)
#undef SYM

    const int EB = (EE + 255) / 256;
    const int MLP_SMEM = (TE2 * 128 * 2 + 8 * 256 + 64 + 512 + 512) * 4 + TE2 * 2 * 4;
    cudaFuncSetAttribute(k_edge_mlp2, cudaFuncAttributeMaxDynamicSharedMemorySize, MLP_SMEM);

    k_init<<<256, 256>>>();

    // ---- GAT layer 1 ----
    k_gemm_nodes<128, 256, 16, 64><<<NN / 16, 64>>>(x, W1, p_proj1);
    k_scores<2><<<NN, 64>>>(p_proj1, a_src1, a_trg1, p_ssrc1, p_strg1);
    k_edge_logits<2><<<EB, 256>>>(ei, p_ssrc1, p_strg1, p_e1, p_max1);
    k_edge_exp<2><<<EB, 256>>>(ei, p_e1, p_max1, p_den1);
    k_edge_agg<2><<<EE / 8, 256>>>(ei, p_e1, p_den1, p_proj1, p_agg1);
    k_finalize1<<<NN, 512>>>(local_emb, b1, p_agg1, p_h);

    // ---- GAT layer 2 ----
    k_gemm_nodes<512, 512, 16, 128><<<NN / 16, 128>>>(p_h, W2, p_proj2);
    k_scores<4><<<NN, 128>>>(p_proj2, a_src2, a_trg2, p_ssrc2, p_strg2);
    k_edge_logits<4><<<EB, 256>>>(ei, p_ssrc2, p_strg2, p_e2, p_max2);
    k_edge_exp<4><<<EB, 256>>>(ei, p_e2, p_max2, p_den2);
    k_edge_agg<4><<<EE / 8, 256>>>(ei, p_e2, p_den2, p_proj2, p_agg2);
    k_finalize2<<<NN, 128>>>(b2, p_agg2, p_out2);

    // ---- edge MLP (factorized first layer, tf32 tensor cores) ----
    k_wprep<<<512, 256>>>(Wi, p_wac, p_wad);
    k_gemm_nodes<128, 1024, 16, 256><<<NN / 16, 256>>>(p_out2, p_wac, p_P);
    k_gemm_nodes<128, 1024, 16, 256><<<NN / 16, 256>>>(p_out2, p_wad, p_Q);
    k_edge_mlp2<<<EE / TE2, 256, MLP_SMEM>>>(ei, p_out2, p_P, p_Q, Wi, bi, Wf1, bf1, Wf2,
                                             bf2, outp);
}

// round 4
// speedup vs baseline: 3.6190x; 2.0853x over previous
#include <cuda_runtime.h>
#include <cuda_bf16.h>
#include <mma.h>
#include <math.h>

using namespace nvcuda;

#define NN 10000
#define EE 160000

// ---------------- device scratch ----------------
__device__ float g_proj1[NN * 256];
__device__ float g_ssrc1[NN * 2];
__device__ float g_strg1[NN * 2];
__device__ float g_e1[EE * 2];
__device__ float g_den1[NN * 2];
__device__ float g_agg1[NN * 256];
__device__ float g_h[NN * 512];
__device__ float g_proj2[NN * 512];
__device__ float g_ssrc2[NN * 4];
__device__ float g_strg2[NN * 4];
__device__ float g_e2[EE * 4];
__device__ float g_den2[NN * 4];
__device__ float g_agg2[NN * 512];
__device__ float g_out2[NN * 128];
__device__ float g_wac[128 * 1024];
__device__ float g_wad[128 * 1024];
__device__ float g_P[NN * 1024];
__device__ float g_Q[NN * 1024];
__device__ __nv_bfloat16 g_wib_h[128 * 1024];   // Wi rows 128..255 (e1*e2 part), bf16
__device__ __nv_bfloat16 g_wf1_h[1024 * 512];   // Wf1, bf16

__device__ __forceinline__ float eluf(float v) { return v > 0.f ? v : expm1f(v); }

__device__ __forceinline__ void red4(float* p, float a, float b, float c, float d) {
    asm volatile("red.global.add.v4.f32 [%0], {%1,%2,%3,%4};"
                 :: "l"(p), "f"(a), "f"(b), "f"(c), "f"(d) : "memory");
}

// ---------------- init ----------------
__global__ void k_init() {
    int i = blockIdx.x * blockDim.x + threadIdx.x;
    int stride = gridDim.x * blockDim.x;
    for (int j = i; j < NN * 256; j += stride) g_agg1[j] = 0.f;
    for (int j = i; j < NN * 512; j += stride) g_agg2[j] = 0.f;
    for (int j = i; j < NN * 2; j += stride) g_den1[j] = 0.f;
    for (int j = i; j < NN * 4; j += stride) g_den2[j] = 0.f;
}

// ---------------- batched node GEMM ----------------
template <int K, int COLS, int NB, int THREADS>
__global__ void k_gemm_nodes(const float* __restrict__ X, const float* __restrict__ W,
                             float* __restrict__ out) {
    __shared__ float xs[NB * K];
    int n0 = blockIdx.x * NB;
    for (int i = threadIdx.x; i < NB * K; i += THREADS) xs[i] = X[(size_t)n0 * K + i];
    __syncthreads();
    int c0 = threadIdx.x * 4;
    float4 acc[NB];
#pragma unroll
    for (int nb = 0; nb < NB; nb++) acc[nb] = make_float4(0.f, 0.f, 0.f, 0.f);
#pragma unroll 2
    for (int k = 0; k < K; k++) {
        float4 wv = *(const float4*)(W + (size_t)k * COLS + c0);
#pragma unroll
        for (int nb = 0; nb < NB; nb++) {
            float x = xs[nb * K + k];
            acc[nb].x += x * wv.x; acc[nb].y += x * wv.y;
            acc[nb].z += x * wv.z; acc[nb].w += x * wv.w;
        }
    }
#pragma unroll
    for (int nb = 0; nb < NB; nb++)
        *(float4*)(out + (size_t)(n0 + nb) * COLS + c0) = acc[nb];
}

// ---------------- attention score projections ----------------
template <int H>
__global__ void k_scores(const float* __restrict__ proj, const float* __restrict__ asrc,
                         const float* __restrict__ atrg, float* __restrict__ ssrc,
                         float* __restrict__ strg) {
    int n = blockIdx.x;
    int h = threadIdx.x >> 5, lane = threadIdx.x & 31;
    float4 p = *(const float4*)(proj + ((size_t)n * H + h) * 128 + lane * 4);
    float4 a = *(const float4*)(asrc + h * 128 + lane * 4);
    float4 b = *(const float4*)(atrg + h * 128 + lane * 4);
    float ps = p.x * a.x + p.y * a.y + p.z * a.z + p.w * a.w;
    float pt = p.x * b.x + p.y * b.y + p.z * b.z + p.w * b.w;
#pragma unroll
    for (int o = 16; o > 0; o >>= 1) {
        ps += __shfl_down_sync(0xffffffffu, ps, o);
        pt += __shfl_down_sync(0xffffffffu, pt, o);
    }
    if (lane == 0) { ssrc[n * H + h] = ps; strg[n * H + h] = pt; }
}

// ---------------- merged edge softmax pass: ex = exp(leakyrelu(.)), denom ----
// NOTE: attention ex/sum(ex) is invariant to the reference's global-max shift,
// so we skip the max entirely (logits are O(1), no overflow risk).
template <int H>
__global__ void k_edge_softmax(const int* __restrict__ ei, const float* __restrict__ ss,
                               const float* __restrict__ st, float* __restrict__ eb,
                               float* __restrict__ den) {
    int i = blockIdx.x * blockDim.x + threadIdx.x;
    if (i >= EE) return;
    int s = ei[i], t = ei[EE + i];
#pragma unroll
    for (int h = 0; h < H; h++) {
        float v = ss[s * H + h] + st[t * H + h];
        v = v > 0.f ? v : 0.2f * v;
        float ex = expf(v);
        eb[(size_t)i * H + h] = ex;
        atomicAdd(&den[t * H + h], ex);
    }
}

// ---------------- scatter attention-weighted messages (vector red) ----------
template <int H>
__global__ void k_edge_agg(const int* __restrict__ ei, const float* __restrict__ eb,
                           const float* __restrict__ den, const float* __restrict__ proj,
                           float* __restrict__ agg) {
    int g = blockIdx.x * blockDim.x + threadIdx.x;
    int i = g >> 5, lane = g & 31;
    if (i >= EE) return;
    int s = ei[i], t = ei[EE + i];
#pragma unroll
    for (int h = 0; h < H; h++) {
        float att = eb[(size_t)i * H + h] / (den[t * H + h] + 1e-16f);
        float4 p = *(const float4*)(proj + ((size_t)s * H + h) * 128 + lane * 4);
        float* d = agg + ((size_t)t * H + h) * 128 + lane * 4;
        red4(d, p.x * att, p.y * att, p.z * att, p.w * att);
    }
}

__global__ void k_finalize1(const float* __restrict__ local_emb, const float* __restrict__ b1,
                            const float* __restrict__ agg, float* __restrict__ hbuf) {
    int n = blockIdx.x, c = threadIdx.x;
    int h = c >> 8, j = c & 255;
    float v = (j < 128) ? agg[(size_t)n * 256 + h * 128 + j]
                        : local_emb[(size_t)n * 128 + (j - 128)];
    v += b1[c];
    hbuf[(size_t)n * 512 + c] = eluf(v);
}

__global__ void k_finalize2(const float* __restrict__ b2, const float* __restrict__ agg,
                            float* __restrict__ out2) {
    int n = blockIdx.x, f = threadIdx.x;
    const float* a = agg + (size_t)n * 512;
    float v = 0.25f * (a[f] + a[128 + f] + a[256 + f] + a[384 + f]) + b2[f];
    out2[(size_t)n * 128 + f] = eluf(v);
}

// ---------------- MLP weight prep ----------------
__global__ void k_wprep(const float* __restrict__ Wi, float* __restrict__ wac,
                        float* __restrict__ wad, __nv_bfloat16* __restrict__ wibh) {
    int i = blockIdx.x * blockDim.x + threadIdx.x;
    if (i >= 128 * 1024) return;
    int f = i >> 10, j = i & 1023;
    float a = Wi[i];
    wac[i] = a + Wi[(size_t)(256 + f) * 1024 + j];
    wad[i] = a + Wi[(size_t)(384 + f) * 1024 + j];
    wibh[i] = __float2bfloat16(Wi[(size_t)(128 + f) * 1024 + j]);
}

__global__ void k_cvt_wf1(const float* __restrict__ Wf1, __nv_bfloat16* __restrict__ out) {
    int i = blockIdx.x * blockDim.x + threadIdx.x;
    if (i < 1024 * 512) out[i] = __float2bfloat16(Wf1[i]);
}

// ---------------- fused per-edge MLP, bf16 wmma with smem-staged weights ----
// 64 edges/block, 256 threads (8 warps).
// Padded ldm: msh/ch 136 bf16, wB1 136, wB2 520, chf 132 f32 (16B/row rotation
// -> conflict-free ldmatrix).
#define TE3 64
#define LDA 136
#define LDB2 520
#define LDCF 132

typedef wmma::fragment<wmma::matrix_a, 16, 16, 16, __nv_bfloat16, wmma::row_major> FragA;
typedef wmma::fragment<wmma::matrix_b, 16, 16, 16, __nv_bfloat16, wmma::row_major> FragB;
typedef wmma::fragment<wmma::accumulator, 16, 16, 16, float> FragC;

__global__ __launch_bounds__(256, 1) void k_edge_mlp3(
    const int* __restrict__ ei, const float* __restrict__ out2,
    const float* __restrict__ P, const float* __restrict__ Q,
    const __nv_bfloat16* __restrict__ WibH, const float* __restrict__ bi,
    const __nv_bfloat16* __restrict__ Wf1H, const float* __restrict__ bf1,
    const float* __restrict__ Wf2, const float* __restrict__ bf2,
    float* __restrict__ outp) {
    extern __shared__ char smemc[];
    __nv_bfloat16* msh = (__nv_bfloat16*)smemc;                 // 64*136  (17408 B)
    __nv_bfloat16* ch = msh + 64 * LDA;                         // 64*136  (17408 B)
    __nv_bfloat16* wB1 = ch + 64 * LDA;                         // 128*136 (34816 B)
    __nv_bfloat16* wB2 = wB1 + 128 * LDA;                       // 32*520 / chf 64*132 (33792 B)
    float* chf = (float*)wB2;
    float* bf1s = (float*)((char*)wB2 + 33792);                 // 512 f
    float* wf2s = bf1s + 512;                                   // 512 f
    float* partial = wf2s + 512;                                // 64 f
    int* sidx = (int*)(partial + 64);                           // 64
    int* tidx = sidx + 64;                                      // 64
    float* scr = (float*)ch;                                    // epilogue alias (8 KB used)

    int tid = threadIdx.x, w = tid >> 5, lane = tid & 31;
    int e0 = blockIdx.x * TE3;

    if (tid < TE3) {
        sidx[tid] = ei[e0 + tid];
        tidx[tid] = ei[EE + e0 + tid];
        partial[tid] = 0.f;
    }
    for (int i = tid; i < 512; i += 256) { bf1s[i] = bf1[i]; wf2s[i] = Wf2[i]; }
    __syncthreads();

    // msh = bf16(e1 * e2)
    for (int idx = tid; idx < TE3 * 32; idx += 256) {
        int e = idx >> 5, j = (idx & 31) * 4;
        float4 a = *(const float4*)(out2 + (size_t)sidx[e] * 128 + j);
        float4 b = *(const float4*)(out2 + (size_t)tidx[e] * 128 + j);
        __nv_bfloat162* mp = (__nv_bfloat162*)(msh + e * LDA + j);
        mp[0] = __floats2bfloat162_rn(a.x * b.x, a.y * b.y);
        mp[1] = __floats2bfloat162_rn(a.z * b.z, a.w * b.w);
    }

    FragC hacc[4][4];
#pragma unroll
    for (int mt = 0; mt < 4; mt++)
#pragma unroll
        for (int nt = 0; nt < 4; nt++) wmma::fill_fragment(hacc[mt][nt], 0.f);

    const int mt1 = w & 3;
    const int nb1 = (w >> 2) * 4;

    for (int c = 0; c < 8; c++) {
        int jb = c << 7;
        __syncthreads();  // prev chunk fully done (wB2/chf free, wB1 free)
        // ---- stage wB1 = bf16 Wi_b[:, jb:jb+128] ----
        {
            const uint4* src = (const uint4*)(WibH) + (jb >> 3);
            uint4* dst = (uint4*)wB1;
#pragma unroll
            for (int i = tid; i < 2048; i += 256) {
                int r = i >> 4, cc = i & 15;
                dst[r * 17 + cc] = src[r * 128 + cc];
            }
        }
        __syncthreads();
        // ---- GEMM1: acc1 = msh @ wB1 ----
        FragC acc1[4];
#pragma unroll
        for (int nt = 0; nt < 4; nt++) wmma::fill_fragment(acc1[nt], 0.f);
#pragma unroll
        for (int k0 = 0; k0 < 8; k0++) {
            FragA a;
            wmma::load_matrix_sync(a, msh + (mt1 * 16) * LDA + k0 * 16, LDA);
#pragma unroll
            for (int nt = 0; nt < 4; nt++) {
                FragB b;
                wmma::load_matrix_sync(b, wB1 + (k0 * 16) * LDA + (nb1 + nt) * 16, LDA);
                wmma::mma_sync(acc1[nt], a, b, acc1[nt]);
            }
        }
#pragma unroll
        for (int nt = 0; nt < 4; nt++)
            wmma::store_matrix_sync(chf + (mt1 * 16) * LDCF + (nb1 + nt) * 16, acc1[nt],
                                    LDCF, wmma::mem_row_major);
        __syncthreads();
        // ---- elementwise: ch = bf16(relu(chf + P + Q + bi)) ----
        for (int idx = tid; idx < TE3 * 32; idx += 256) {
            int e = idx >> 5, j = (idx & 31) * 4;
            float4 v = *(float4*)(chf + e * LDCF + j);
            float4 p = *(const float4*)(P + (size_t)sidx[e] * 1024 + jb + j);
            float4 q = *(const float4*)(Q + (size_t)tidx[e] * 1024 + jb + j);
            float4 bv = *(const float4*)(bi + jb + j);
            v.x = fmaxf(v.x + p.x + q.x + bv.x, 0.f);
            v.y = fmaxf(v.y + p.y + q.y + bv.y, 0.f);
            v.z = fmaxf(v.z + p.z + q.z + bv.z, 0.f);
            v.w = fmaxf(v.w + p.w + q.w + bv.w, 0.f);
            __nv_bfloat162* cp = (__nv_bfloat162*)(ch + e * LDA + j);
            cp[0] = __floats2bfloat162_rn(v.x, v.y);
            cp[1] = __floats2bfloat162_rn(v.z, v.w);
        }
        // ---- GEMM2: hacc += ch @ Wf1[jb:jb+128, :], k staged in 4 substages ----
        for (int ks = 0; ks < 4; ks++) {
            __syncthreads();  // prev substage mma done / elementwise done (chf==wB2 free)
            const uint4* src = (const uint4*)(Wf1H + (size_t)(jb + ks * 32) * 512);
            uint4* dst = (uint4*)wB2;
#pragma unroll
            for (int i = tid; i < 2048; i += 256) {
                int r = i >> 6, cc = i & 63;
                dst[r * 65 + cc] = src[r * 64 + cc];
            }
            __syncthreads();
#pragma unroll
            for (int k2 = 0; k2 < 2; k2++) {
                FragA a[4];
#pragma unroll
                for (int mt = 0; mt < 4; mt++)
                    wmma::load_matrix_sync(a[mt], ch + (mt * 16) * LDA + ks * 32 + k2 * 16, LDA);
#pragma unroll
                for (int nt = 0; nt < 4; nt++) {
                    FragB b;
                    wmma::load_matrix_sync(b, wB2 + (k2 * 16) * LDB2 + w * 64 + nt * 16, LDB2);
#pragma unroll
                    for (int mt = 0; mt < 4; mt++)
                        wmma::mma_sync(hacc[mt][nt], a[mt], b, hacc[mt][nt]);
                }
            }
        }
    }
    __syncthreads();

    // ---- epilogue: partial[m] += sum_n relu(hdn+bf1)*Wf2 ----
    float* myscr = scr + w * 256;
#pragma unroll
    for (int mt = 0; mt < 4; mt++) {
#pragma unroll
        for (int nt = 0; nt < 4; nt++) {
            wmma::store_matrix_sync(myscr, hacc[mt][nt], 16, wmma::mem_row_major);
            __syncwarp();
            int r = lane & 15, cc0 = (lane >> 4) * 8;
            int n0 = w * 64 + nt * 16 + cc0;
            float s = 0.f;
#pragma unroll
            for (int cc = 0; cc < 8; cc++) {
                float v = myscr[r * 16 + cc0 + cc];
                int n = n0 + cc;
                s += fmaxf(v + bf1s[n], 0.f) * wf2s[n];
            }
            atomicAdd(&partial[mt * 16 + r], s);
            __syncwarp();
        }
    }
    __syncthreads();
    if (tid < TE3) {
        float lg = partial[tid] + bf2[0];
        outp[e0 + tid] = 1.f / (1.f + expf(-lg));
    }
}

// ---------------- launch ----------------
extern "C" void kernel_launch(void* const* d_in, const int* in_sizes, int n_in,
                              void* d_out, int out_size) {
    const float* x = (const float*)d_in[0];
    const int* ei = (const int*)d_in[1];
    const float* local_emb = (const float*)d_in[2];
    const float* W1 = (const float*)d_in[3];
    const float* a_src1 = (const float*)d_in[4];
    const float* a_trg1 = (const float*)d_in[5];
    const float* b1 = (const float*)d_in[6];
    const float* W2 = (const float*)d_in[7];
    const float* a_src2 = (const float*)d_in[8];
    const float* a_trg2 = (const float*)d_in[9];
    const float* b2 = (const float*)d_in[10];
    const float* Wi = (const float*)d_in[11];
    const float* bi = (const float*)d_in[12];
    const float* Wf1 = (const float*)d_in[13];
    const float* bf1 = (const float*)d_in[14];
    const float* Wf2 = (const float*)d_in[15];
    const float* bf2 = (const float*)d_in[16];
    float* outp = (float*)d_out;

    void* tmp;
    float *p_proj1, *p_ssrc1, *p_strg1, *p_e1, *p_den1, *p_agg1, *p_h;
    float *p_proj2, *p_ssrc2, *p_strg2, *p_e2, *p_den2, *p_agg2, *p_out2;
    float *p_wac, *p_wad, *p_P, *p_Q;
    __nv_bfloat16 *p_wibh, *p_wf1h;
#define SYM(p, s) cudaGetSymbolAddress(&tmp, s); p = (decltype(p))tmp;
    SYM(p_proj1, g_proj1) SYM(p_ssrc1, g_ssrc1) SYM(p_strg1, g_strg1)
    SYM(p_e1, g_e1) SYM(p_den1, g_den1) SYM(p_agg1, g_agg1) SYM(p_h, g_h)
    SYM(p_proj2, g_proj2) SYM(p_ssrc2, g_ssrc2) SYM(p_strg2, g_strg2)
    SYM(p_e2, g_e2) SYM(p_den2, g_den2) SYM(p_agg2, g_agg2) SYM(p_out2, g_out2)
    SYM(p_wac, g_wac) SYM(p_wad, g_wad) SYM(p_P, g_P) SYM(p_Q, g_Q)
    SYM(p_wibh, g_wib_h) SYM(p_wf1h, g_wf1_h)
#undef SYM

    const int EB = (EE + 255) / 256;
    const int MLP_SMEM = 17408 * 2 + 34816 + 33792 + (512 + 512 + 64) * 4 + 128 * 4;
    cudaFuncSetAttribute(k_edge_mlp3, cudaFuncAttributeMaxDynamicSharedMemorySize, MLP_SMEM);

    k_init<<<256, 256>>>();
    // weight preps (independent of graph data)
    k_wprep<<<512, 256>>>(Wi, p_wac, p_wad, p_wibh);
    k_cvt_wf1<<<2048, 256>>>(Wf1, p_wf1h);

    // ---- GAT layer 1 ----
    k_gemm_nodes<128, 256, 16, 64><<<NN / 16, 64>>>(x, W1, p_proj1);
    k_scores<2><<<NN, 64>>>(p_proj1, a_src1, a_trg1, p_ssrc1, p_strg1);
    k_edge_softmax<2><<<EB, 256>>>(ei, p_ssrc1, p_strg1, p_e1, p_den1);
    k_edge_agg<2><<<EE / 8, 256>>>(ei, p_e1, p_den1, p_proj1, p_agg1);
    k_finalize1<<<NN, 512>>>(local_emb, b1, p_agg1, p_h);

    // ---- GAT layer 2 ----
    k_gemm_nodes<512, 512, 16, 128><<<NN / 16, 128>>>(p_h, W2, p_proj2);
    k_scores<4><<<NN, 128>>>(p_proj2, a_src2, a_trg2, p_ssrc2, p_strg2);
    k_edge_softmax<4><<<EB, 256>>>(ei, p_ssrc2, p_strg2, p_e2, p_den2);
    k_edge_agg<4><<<EE / 8, 256>>>(ei, p_e2, p_den2, p_proj2, p_agg2);
    k_finalize2<<<NN, 128>>>(b2, p_agg2, p_out2);

    // ---- per-node MLP factor GEMMs ----
    k_gemm_nodes<128, 1024, 16, 256><<<NN / 16, 256>>>(p_out2, p_wac, p_P);
    k_gemm_nodes<128, 1024, 16, 256><<<NN / 16, 256>>>(p_out2, p_wad, p_Q);

    // ---- fused edge MLP (bf16 tensor cores, smem-staged weights) ----
    k_edge_mlp3<<<EE / TE3, 256, MLP_SMEM>>>(ei, p_out2, p_P, p_Q, p_wibh, bi, p_wf1h,
                                             bf1, Wf2, bf2, outp);
}

// round 5
// speedup vs baseline: 4.1482x; 1.1462x over previous
#include <cuda_runtime.h>
#include <cuda_bf16.h>
#include <mma.h>
#include <math.h>

using namespace nvcuda;

#define NN 10000
#define NP 10112   // padded to multiple of 128 for GEMM tiles
#define EE 160000

// ---------------- device scratch ----------------
__device__ float g_proj1[NP * 256];
__device__ float g_ssrc1[NN * 2];
__device__ float g_strg1[NN * 2];
__device__ float g_e1[EE * 2];
__device__ float g_den1[NN * 2];
__device__ float g_agg1[NN * 256];
__device__ float g_h[NP * 512];
__device__ float g_proj2[NP * 512];
__device__ float g_ssrc2[NN * 4];
__device__ float g_strg2[NN * 4];
__device__ float g_e2[EE * 4];
__device__ float g_den2[NN * 4];
__device__ float g_agg2[NN * 512];
__device__ float g_out2[NP * 128];
__device__ float g_PQ[NP * 2048];                 // [:,0:1024]=P, [:,1024:2048]=Q
__device__ __nv_bfloat16 g_wacad[128 * 2048];     // [Wi_a+Wi_c | Wi_a+Wi_d] bf16
__device__ __nv_bfloat16 g_wib_h[128 * 1024];     // Wi rows 128..255, bf16
__device__ __nv_bfloat16 g_wf1_h[1024 * 512];     // Wf1 bf16

__device__ __forceinline__ float eluf(float v) { return v > 0.f ? v : expm1f(v); }

__device__ __forceinline__ void red4(float* p, float a, float b, float c, float d) {
    asm volatile("red.global.add.v4.f32 [%0], {%1,%2,%3,%4};"
                 :: "l"(p), "f"(a), "f"(b), "f"(c), "f"(d) : "memory");
}

// ---------------- init ----------------
__global__ void k_init() {
    int i = blockIdx.x * blockDim.x + threadIdx.x;
    int stride = gridDim.x * blockDim.x;
    for (int j = i; j < NN * 256; j += stride) g_agg1[j] = 0.f;
    for (int j = i; j < NN * 512; j += stride) g_agg2[j] = 0.f;
    for (int j = i; j < NN * 2; j += stride) g_den1[j] = 0.f;
    for (int j = i; j < NN * 4; j += stride) g_den2[j] = 0.f;
}

// =================== tf32 tensor-core GEMM ===================
// C[128 x 128 tile] = A[M x K] @ W[K x COLS]; A fp32 (rows >= NN read as 0),
// C is padded scratch (unguarded stores). 8 warps: warp tile 64x32 (2m x 4n grid).
template <int K, int COLS>
__global__ __launch_bounds__(256) void k_gemm_tf32(const float* __restrict__ A,
                                                   const float* __restrict__ W,
                                                   float* __restrict__ C) {
    constexpr int KC = 32;
    __shared__ float As[128][36];
    __shared__ float Ws[KC][132];
    int m0 = blockIdx.x * 128, n0 = blockIdx.y * 128;
    int tid = threadIdx.x, w = tid >> 5;
    int wm = w & 1, wn = w >> 1;

    wmma::fragment<wmma::accumulator, 16, 16, 8, float> acc[4][2];
#pragma unroll
    for (int mt = 0; mt < 4; mt++)
#pragma unroll
        for (int nt = 0; nt < 2; nt++) wmma::fill_fragment(acc[mt][nt], 0.f);

    for (int kc = 0; kc < K; kc += KC) {
        __syncthreads();
#pragma unroll
        for (int i = tid; i < 1024; i += 256) {
            int r = i >> 3, c = (i & 7) * 4;
            int gm = m0 + r;
            float4 v = (gm < NN) ? *(const float4*)(A + (size_t)gm * K + kc + c)
                                 : make_float4(0.f, 0.f, 0.f, 0.f);
            *(float4*)(&As[r][c]) = v;
        }
#pragma unroll
        for (int i = tid; i < 1024; i += 256) {
            int r = i >> 5, c = (i & 31) * 4;
            float4 v = *(const float4*)(W + (size_t)(kc + r) * COLS + n0 + c);
            *(float4*)(&Ws[r][c]) = v;
        }
        __syncthreads();
#pragma unroll
        for (int k8 = 0; k8 < KC / 8; k8++) {
            wmma::fragment<wmma::matrix_a, 16, 16, 8, wmma::precision::tf32,
                           wmma::row_major> a[4];
#pragma unroll
            for (int mt = 0; mt < 4; mt++) {
                wmma::load_matrix_sync(a[mt], &As[wm * 64 + mt * 16][k8 * 8], 36);
#pragma unroll
                for (int i = 0; i < a[mt].num_elements; i++)
                    a[mt].x[i] = wmma::__float_to_tf32(a[mt].x[i]);
            }
#pragma unroll
            for (int nt = 0; nt < 2; nt++) {
                wmma::fragment<wmma::matrix_b, 16, 16, 8, wmma::precision::tf32,
                               wmma::row_major> b;
                wmma::load_matrix_sync(b, &Ws[k8 * 8][wn * 32 + nt * 16], 132);
#pragma unroll
                for (int i = 0; i < b.num_elements; i++)
                    b.x[i] = wmma::__float_to_tf32(b.x[i]);
#pragma unroll
                for (int mt = 0; mt < 4; mt++)
                    wmma::mma_sync(acc[mt][nt], a[mt], b, acc[mt][nt]);
            }
        }
    }
#pragma unroll
    for (int mt = 0; mt < 4; mt++)
#pragma unroll
        for (int nt = 0; nt < 2; nt++) {
            int gm = m0 + wm * 64 + mt * 16;
            wmma::store_matrix_sync(C + (size_t)gm * COLS + n0 + wn * 32 + nt * 16,
                                    acc[mt][nt], COLS, wmma::mem_row_major);
        }
}

// =================== bf16 tensor-core GEMM (A fp32 converted on stage) =======
template <int K, int COLS>
__global__ __launch_bounds__(256) void k_gemm_bf16(const float* __restrict__ A,
                                                   const __nv_bfloat16* __restrict__ W,
                                                   float* __restrict__ C) {
    constexpr int KC = 32;
    __shared__ __nv_bfloat16 As[128][40];
    __shared__ __nv_bfloat16 Ws[KC][136];
    int m0 = blockIdx.x * 128, n0 = blockIdx.y * 128;
    int tid = threadIdx.x, w = tid >> 5;
    int wm = w & 1, wn = w >> 1;

    wmma::fragment<wmma::accumulator, 16, 16, 16, float> acc[4][2];
#pragma unroll
    for (int mt = 0; mt < 4; mt++)
#pragma unroll
        for (int nt = 0; nt < 2; nt++) wmma::fill_fragment(acc[mt][nt], 0.f);

    for (int kc = 0; kc < K; kc += KC) {
        __syncthreads();
#pragma unroll
        for (int i = tid; i < 1024; i += 256) {
            int r = i >> 3, c = (i & 7) * 4;
            int gm = m0 + r;
            float4 v = (gm < NN) ? *(const float4*)(A + (size_t)gm * K + kc + c)
                                 : make_float4(0.f, 0.f, 0.f, 0.f);
            __nv_bfloat162* dp = (__nv_bfloat162*)(&As[r][c]);
            dp[0] = __floats2bfloat162_rn(v.x, v.y);
            dp[1] = __floats2bfloat162_rn(v.z, v.w);
        }
#pragma unroll
        for (int i = tid; i < 512; i += 256) {
            int r = i >> 4, c = (i & 15) * 8;
            *(uint4*)(&Ws[r][c]) =
                *(const uint4*)(W + (size_t)(kc + r) * COLS + n0 + c);
        }
        __syncthreads();
#pragma unroll
        for (int k16 = 0; k16 < KC / 16; k16++) {
            wmma::fragment<wmma::matrix_a, 16, 16, 16, __nv_bfloat16, wmma::row_major> a[4];
#pragma unroll
            for (int mt = 0; mt < 4; mt++)
                wmma::load_matrix_sync(a[mt], &As[wm * 64 + mt * 16][k16 * 16], 40);
#pragma unroll
            for (int nt = 0; nt < 2; nt++) {
                wmma::fragment<wmma::matrix_b, 16, 16, 16, __nv_bfloat16, wmma::row_major> b;
                wmma::load_matrix_sync(b, &Ws[k16 * 16][wn * 32 + nt * 16], 136);
#pragma unroll
                for (int mt = 0; mt < 4; mt++)
                    wmma::mma_sync(acc[mt][nt], a[mt], b, acc[mt][nt]);
            }
        }
    }
#pragma unroll
    for (int mt = 0; mt < 4; mt++)
#pragma unroll
        for (int nt = 0; nt < 2; nt++) {
            int gm = m0 + wm * 64 + mt * 16;
            wmma::store_matrix_sync(C + (size_t)gm * COLS + n0 + wn * 32 + nt * 16,
                                    acc[mt][nt], COLS, wmma::mem_row_major);
        }
}

// ---------------- attention score projections ----------------
template <int H>
__global__ void k_scores(const float* __restrict__ proj, const float* __restrict__ asrc,
                         const float* __restrict__ atrg, float* __restrict__ ssrc,
                         float* __restrict__ strg) {
    int n = blockIdx.x;
    int h = threadIdx.x >> 5, lane = threadIdx.x & 31;
    float4 p = *(const float4*)(proj + ((size_t)n * H + h) * 128 + lane * 4);
    float4 a = *(const float4*)(asrc + h * 128 + lane * 4);
    float4 b = *(const float4*)(atrg + h * 128 + lane * 4);
    float ps = p.x * a.x + p.y * a.y + p.z * a.z + p.w * a.w;
    float pt = p.x * b.x + p.y * b.y + p.z * b.z + p.w * b.w;
#pragma unroll
    for (int o = 16; o > 0; o >>= 1) {
        ps += __shfl_down_sync(0xffffffffu, ps, o);
        pt += __shfl_down_sync(0xffffffffu, pt, o);
    }
    if (lane == 0) { ssrc[n * H + h] = ps; strg[n * H + h] = pt; }
}

// ---------------- merged edge softmax (global-max shift is a no-op) ----------
template <int H>
__global__ void k_edge_softmax(const int* __restrict__ ei, const float* __restrict__ ss,
                               const float* __restrict__ st, float* __restrict__ eb,
                               float* __restrict__ den) {
    int i = blockIdx.x * blockDim.x + threadIdx.x;
    if (i >= EE) return;
    int s = ei[i], t = ei[EE + i];
#pragma unroll
    for (int h = 0; h < H; h++) {
        float v = ss[s * H + h] + st[t * H + h];
        v = v > 0.f ? v : 0.2f * v;
        float ex = expf(v);
        eb[(size_t)i * H + h] = ex;
        atomicAdd(&den[t * H + h], ex);
    }
}

// ---------------- scatter attention-weighted messages ----------------
template <int H>
__global__ void k_edge_agg(const int* __restrict__ ei, const float* __restrict__ eb,
                           const float* __restrict__ den, const float* __restrict__ proj,
                           float* __restrict__ agg) {
    int g = blockIdx.x * blockDim.x + threadIdx.x;
    int i = g >> 5, lane = g & 31;
    if (i >= EE) return;
    int s = ei[i], t = ei[EE + i];
#pragma unroll
    for (int h = 0; h < H; h++) {
        float att = eb[(size_t)i * H + h] / (den[t * H + h] + 1e-16f);
        float4 p = *(const float4*)(proj + ((size_t)s * H + h) * 128 + lane * 4);
        float* d = agg + ((size_t)t * H + h) * 128 + lane * 4;
        red4(d, p.x * att, p.y * att, p.z * att, p.w * att);
    }
}

__global__ void k_finalize1(const float* __restrict__ local_emb, const float* __restrict__ b1,
                            const float* __restrict__ agg, float* __restrict__ hbuf) {
    int n = blockIdx.x, c = threadIdx.x;
    int h = c >> 8, j = c & 255;
    float v = (j < 128) ? agg[(size_t)n * 256 + h * 128 + j]
                        : local_emb[(size_t)n * 128 + (j - 128)];
    v += b1[c];
    hbuf[(size_t)n * 512 + c] = eluf(v);
}

__global__ void k_finalize2(const float* __restrict__ b2, const float* __restrict__ agg,
                            float* __restrict__ out2) {
    int n = blockIdx.x, f = threadIdx.x;
    const float* a = agg + (size_t)n * 512;
    float v = 0.25f * (a[f] + a[128 + f] + a[256 + f] + a[384 + f]) + b2[f];
    out2[(size_t)n * 128 + f] = eluf(v);
}

// ---------------- MLP weight prep ----------------
__global__ void k_wprep(const float* __restrict__ Wi, __nv_bfloat16* __restrict__ wacad,
                        __nv_bfloat16* __restrict__ wibh) {
    int i = blockIdx.x * blockDim.x + threadIdx.x;
    if (i >= 128 * 2048) return;
    int k = i >> 11, j = i & 2047;
    float v;
    if (j < 1024)
        v = Wi[(size_t)k * 1024 + j] + Wi[(size_t)(256 + k) * 1024 + j];
    else
        v = Wi[(size_t)k * 1024 + (j - 1024)] + Wi[(size_t)(384 + k) * 1024 + (j - 1024)];
    wacad[i] = __float2bfloat16(v);
    if (j < 1024) wibh[(size_t)k * 1024 + j] = __float2bfloat16(Wi[(size_t)(128 + k) * 1024 + j]);
}

__global__ void k_cvt_wf1(const float* __restrict__ Wf1, __nv_bfloat16* __restrict__ out) {
    int i = blockIdx.x * blockDim.x + threadIdx.x;
    if (i < 1024 * 512) out[i] = __float2bfloat16(Wf1[i]);
}

// ---------------- fused per-edge MLP, bf16 wmma ----------------
#define TE3 64
#define LDA 136
#define LDB2 520
#define LDCF 132

typedef wmma::fragment<wmma::matrix_a, 16, 16, 16, __nv_bfloat16, wmma::row_major> FragA;
typedef wmma::fragment<wmma::matrix_b, 16, 16, 16, __nv_bfloat16, wmma::row_major> FragB;
typedef wmma::fragment<wmma::accumulator, 16, 16, 16, float> FragC;

__global__ __launch_bounds__(256, 1) void k_edge_mlp3(
    const int* __restrict__ ei, const float* __restrict__ out2,
    const float* __restrict__ PQ,
    const __nv_bfloat16* __restrict__ WibH, const float* __restrict__ bi,
    const __nv_bfloat16* __restrict__ Wf1H, const float* __restrict__ bf1,
    const float* __restrict__ Wf2, const float* __restrict__ bf2,
    float* __restrict__ outp) {
    extern __shared__ char smemc[];
    __nv_bfloat16* msh = (__nv_bfloat16*)smemc;
    __nv_bfloat16* ch = msh + 64 * LDA;
    __nv_bfloat16* wB1 = ch + 64 * LDA;
    __nv_bfloat16* wB2 = wB1 + 128 * LDA;
    float* chf = (float*)wB2;
    float* bf1s = (float*)((char*)wB2 + 33792);
    float* wf2s = bf1s + 512;
    float* partial = wf2s + 512;
    int* sidx = (int*)(partial + 64);
    int* tidx = sidx + 64;
    float* scr = (float*)ch;

    int tid = threadIdx.x, w = tid >> 5, lane = tid & 31;
    int e0 = blockIdx.x * TE3;

    if (tid < TE3) {
        sidx[tid] = ei[e0 + tid];
        tidx[tid] = ei[EE + e0 + tid];
        partial[tid] = 0.f;
    }
    for (int i = tid; i < 512; i += 256) { bf1s[i] = bf1[i]; wf2s[i] = Wf2[i]; }
    __syncthreads();

    for (int idx = tid; idx < TE3 * 32; idx += 256) {
        int e = idx >> 5, j = (idx & 31) * 4;
        float4 a = *(const float4*)(out2 + (size_t)sidx[e] * 128 + j);
        float4 b = *(const float4*)(out2 + (size_t)tidx[e] * 128 + j);
        __nv_bfloat162* mp = (__nv_bfloat162*)(msh + e * LDA + j);
        mp[0] = __floats2bfloat162_rn(a.x * b.x, a.y * b.y);
        mp[1] = __floats2bfloat162_rn(a.z * b.z, a.w * b.w);
    }

    FragC hacc[4][4];
#pragma unroll
    for (int mt = 0; mt < 4; mt++)
#pragma unroll
        for (int nt = 0; nt < 4; nt++) wmma::fill_fragment(hacc[mt][nt], 0.f);

    const int mt1 = w & 3;
    const int nb1 = (w >> 2) * 4;

    for (int c = 0; c < 8; c++) {
        int jb = c << 7;
        __syncthreads();
        {
            const uint4* src = (const uint4*)(WibH) + (jb >> 3);
            uint4* dst = (uint4*)wB1;
#pragma unroll
            for (int i = tid; i < 2048; i += 256) {
                int r = i >> 4, cc = i & 15;
                dst[r * 17 + cc] = src[r * 128 + cc];
            }
        }
        __syncthreads();
        FragC acc1[4];
#pragma unroll
        for (int nt = 0; nt < 4; nt++) wmma::fill_fragment(acc1[nt], 0.f);
#pragma unroll
        for (int k0 = 0; k0 < 8; k0++) {
            FragA a;
            wmma::load_matrix_sync(a, msh + (mt1 * 16) * LDA + k0 * 16, LDA);
#pragma unroll
            for (int nt = 0; nt < 4; nt++) {
                FragB b;
                wmma::load_matrix_sync(b, wB1 + (k0 * 16) * LDA + (nb1 + nt) * 16, LDA);
                wmma::mma_sync(acc1[nt], a, b, acc1[nt]);
            }
        }
#pragma unroll
        for (int nt = 0; nt < 4; nt++)
            wmma::store_matrix_sync(chf + (mt1 * 16) * LDCF + (nb1 + nt) * 16, acc1[nt],
                                    LDCF, wmma::mem_row_major);
        __syncthreads();
        for (int idx = tid; idx < TE3 * 32; idx += 256) {
            int e = idx >> 5, j = (idx & 31) * 4;
            float4 v = *(float4*)(chf + e * LDCF + j);
            float4 p = *(const float4*)(PQ + (size_t)sidx[e] * 2048 + jb + j);
            float4 q = *(const float4*)(PQ + (size_t)tidx[e] * 2048 + 1024 + jb + j);
            float4 bv = *(const float4*)(bi + jb + j);
            v.x = fmaxf(v.x + p.x + q.x + bv.x, 0.f);
            v.y = fmaxf(v.y + p.y + q.y + bv.y, 0.f);
            v.z = fmaxf(v.z + p.z + q.z + bv.z, 0.f);
            v.w = fmaxf(v.w + p.w + q.w + bv.w, 0.f);
            __nv_bfloat162* cp = (__nv_bfloat162*)(ch + e * LDA + j);
            cp[0] = __floats2bfloat162_rn(v.x, v.y);
            cp[1] = __floats2bfloat162_rn(v.z, v.w);
        }
        for (int ks = 0; ks < 4; ks++) {
            __syncthreads();
            const uint4* src = (const uint4*)(Wf1H + (size_t)(jb + ks * 32) * 512);
            uint4* dst = (uint4*)wB2;
#pragma unroll
            for (int i = tid; i < 2048; i += 256) {
                int r = i >> 6, cc = i & 63;
                dst[r * 65 + cc] = src[r * 64 + cc];
            }
            __syncthreads();
#pragma unroll
            for (int k2 = 0; k2 < 2; k2++) {
                FragA a[4];
#pragma unroll
                for (int mt = 0; mt < 4; mt++)
                    wmma::load_matrix_sync(a[mt], ch + (mt * 16) * LDA + ks * 32 + k2 * 16, LDA);
#pragma unroll
                for (int nt = 0; nt < 4; nt++) {
                    FragB b;
                    wmma::load_matrix_sync(b, wB2 + (k2 * 16) * LDB2 + w * 64 + nt * 16, LDB2);
#pragma unroll
                    for (int mt = 0; mt < 4; mt++)
                        wmma::mma_sync(hacc[mt][nt], a[mt], b, hacc[mt][nt]);
                }
            }
        }
    }
    __syncthreads();

    float* myscr = scr + w * 256;
#pragma unroll
    for (int mt = 0; mt < 4; mt++) {
#pragma unroll
        for (int nt = 0; nt < 4; nt++) {
            wmma::store_matrix_sync(myscr, hacc[mt][nt], 16, wmma::mem_row_major);
            __syncwarp();
            int r = lane & 15, cc0 = (lane >> 4) * 8;
            int n0 = w * 64 + nt * 16 + cc0;
            float s = 0.f;
#pragma unroll
            for (int cc = 0; cc < 8; cc++) {
                float v = myscr[r * 16 + cc0 + cc];
                int n = n0 + cc;
                s += fmaxf(v + bf1s[n], 0.f) * wf2s[n];
            }
            atomicAdd(&partial[mt * 16 + r], s);
            __syncwarp();
        }
    }
    __syncthreads();
    if (tid < TE3) {
        float lg = partial[tid] + bf2[0];
        outp[e0 + tid] = 1.f / (1.f + expf(-lg));
    }
}

// ---------------- launch ----------------
extern "C" void kernel_launch(void* const* d_in, const int* in_sizes, int n_in,
                              void* d_out, int out_size) {
    const float* x = (const float*)d_in[0];
    const int* ei = (const int*)d_in[1];
    const float* local_emb = (const float*)d_in[2];
    const float* W1 = (const float*)d_in[3];
    const float* a_src1 = (const float*)d_in[4];
    const float* a_trg1 = (const float*)d_in[5];
    const float* b1 = (const float*)d_in[6];
    const float* W2 = (const float*)d_in[7];
    const float* a_src2 = (const float*)d_in[8];
    const float* a_trg2 = (const float*)d_in[9];
    const float* b2 = (const float*)d_in[10];
    const float* Wi = (const float*)d_in[11];
    const float* bi = (const float*)d_in[12];
    const float* Wf1 = (const float*)d_in[13];
    const float* bf1 = (const float*)d_in[14];
    const float* Wf2 = (const float*)d_in[15];
    const float* bf2 = (const float*)d_in[16];
    float* outp = (float*)d_out;

    void* tmp;
    float *p_proj1, *p_ssrc1, *p_strg1, *p_e1, *p_den1, *p_agg1, *p_h;
    float *p_proj2, *p_ssrc2, *p_strg2, *p_e2, *p_den2, *p_agg2, *p_out2, *p_PQ;
    __nv_bfloat16 *p_wacad, *p_wibh, *p_wf1h;
#define SYM(p, s) cudaGetSymbolAddress(&tmp, s); p = (decltype(p))tmp;
    SYM(p_proj1, g_proj1) SYM(p_ssrc1, g_ssrc1) SYM(p_strg1, g_strg1)
    SYM(p_e1, g_e1) SYM(p_den1, g_den1) SYM(p_agg1, g_agg1) SYM(p_h, g_h)
    SYM(p_proj2, g_proj2) SYM(p_ssrc2, g_ssrc2) SYM(p_strg2, g_strg2)
    SYM(p_e2, g_e2) SYM(p_den2, g_den2) SYM(p_agg2, g_agg2) SYM(p_out2, g_out2)
    SYM(p_PQ, g_PQ) SYM(p_wacad, g_wacad) SYM(p_wibh, g_wib_h) SYM(p_wf1h, g_wf1_h)
#undef SYM

    const int EB = (EE + 255) / 256;
    const int MLP_SMEM = 17408 * 2 + 34816 + 33792 + (512 + 512 + 64) * 4 + 128 * 4;
    cudaFuncSetAttribute(k_edge_mlp3, cudaFuncAttributeMaxDynamicSharedMemorySize, MLP_SMEM);

    k_init<<<256, 256>>>();
    k_wprep<<<1024, 256>>>(Wi, p_wacad, p_wibh);
    k_cvt_wf1<<<2048, 256>>>(Wf1, p_wf1h);

    // ---- GAT layer 1 ----
    k_gemm_tf32<128, 256><<<dim3(NP / 128, 2), 256>>>(x, W1, p_proj1);
    k_scores<2><<<NN, 64>>>(p_proj1, a_src1, a_trg1, p_ssrc1, p_strg1);
    k_edge_softmax<2><<<EB, 256>>>(ei, p_ssrc1, p_strg1, p_e1, p_den1);
    k_edge_agg<2><<<EE / 8, 256>>>(ei, p_e1, p_den1, p_proj1, p_agg1);
    k_finalize1<<<NN, 512>>>(local_emb, b1, p_agg1, p_h);

    // ---- GAT layer 2 ----
    k_gemm_tf32<512, 512><<<dim3(NP / 128, 4), 256>>>(p_h, W2, p_proj2);
    k_scores<4><<<NN, 128>>>(p_proj2, a_src2, a_trg2, p_ssrc2, p_strg2);
    k_edge_softmax<4><<<EB, 256>>>(ei, p_ssrc2, p_strg2, p_e2, p_den2);
    k_edge_agg<4><<<EE / 8, 256>>>(ei, p_e2, p_den2, p_proj2, p_agg2);
    k_finalize2<<<NN, 128>>>(b2, p_agg2, p_out2);

    // ---- P|Q combined bf16 GEMM ----
    k_gemm_bf16<128, 2048><<<dim3(NP / 128, 16), 256>>>(p_out2, p_wacad, p_PQ);

    // ---- fused edge MLP ----
    k_edge_mlp3<<<EE / TE3, 256, MLP_SMEM>>>(ei, p_out2, p_PQ, p_wibh, bi, p_wf1h,
                                             bf1, Wf2, bf2, outp);
}

// round 7
// speedup vs baseline: 4.6386x; 1.1182x over previous
#include <cuda_runtime.h>
#include <cuda_bf16.h>
#include <mma.h>
#include <math.h>
#include <cstdint>

using namespace nvcuda;

#define NN 10000
#define NP 10112
#define EE 160000

// ---------------- device scratch ----------------
__device__ float g_proj1[NP * 256];
__device__ float g_ssrc1[NN * 2];
__device__ float g_strg1[NN * 2];
__device__ float g_e1[EE * 2];
__device__ float g_den1[NN * 2];
__device__ float g_agg1[NN * 256];
__device__ float g_h[NP * 512];
__device__ float g_proj2[NP * 512];
__device__ float g_ssrc2[NN * 4];
__device__ float g_strg2[NN * 4];
__device__ float g_e2[EE * 4];
__device__ float g_den2[NN * 4];
__device__ float g_agg2[NN * 512];
__device__ float g_out2[NP * 128];
__device__ __nv_bfloat16 g_PQh[NP * 2048];        // bf16 [P | Q]
__device__ __nv_bfloat16 g_wacad[128 * 2048];     // [Wi_a+Wi_c | Wi_a+Wi_d] bf16
__device__ __nv_bfloat16 g_wib_h[128 * 1024];     // Wi rows 128..255, bf16
__device__ __nv_bfloat16 g_wf1_h[1024 * 512];     // Wf1 bf16

__device__ __forceinline__ float eluf(float v) { return v > 0.f ? v : expm1f(v); }

__device__ __forceinline__ void red4(float* p, float a, float b, float c, float d) {
    asm volatile("red.global.add.v4.f32 [%0], {%1,%2,%3,%4};"
                 :: "l"(p), "f"(a), "f"(b), "f"(c), "f"(d) : "memory");
}

__device__ __forceinline__ uint32_t smem_u32(const void* p) {
    uint32_t a;
    asm("{ .reg .u64 t; cvta.to.shared.u64 t, %1; cvt.u32.u64 %0, t; }" : "=r"(a) : "l"(p));
    return a;
}
__device__ __forceinline__ void cpa16(uint32_t saddr, const void* g) {
    asm volatile("cp.async.cg.shared.global [%0], [%1], 16;" :: "r"(saddr), "l"(g));
}
#define CP_COMMIT() asm volatile("cp.async.commit_group;" ::: "memory")
#define CP_WAIT0()  asm volatile("cp.async.wait_group 0;" ::: "memory")

// ---------------- init ----------------
__global__ void k_init() {
    int i = blockIdx.x * blockDim.x + threadIdx.x;
    int stride = gridDim.x * blockDim.x;
    for (int j = i; j < NN * 256; j += stride) g_agg1[j] = 0.f;
    for (int j = i; j < NN * 512; j += stride) g_agg2[j] = 0.f;
    for (int j = i; j < NN * 2; j += stride) g_den1[j] = 0.f;
    for (int j = i; j < NN * 4; j += stride) g_den2[j] = 0.f;
}

// =================== tf32 tensor-core GEMM ===================
template <int K, int COLS>
__global__ __launch_bounds__(256) void k_gemm_tf32(const float* __restrict__ A,
                                                   const float* __restrict__ W,
                                                   float* __restrict__ C) {
    constexpr int KC = 32;
    __shared__ float As[128][36];
    __shared__ float Ws[KC][132];
    int m0 = blockIdx.x * 128, n0 = blockIdx.y * 128;
    int tid = threadIdx.x, w = tid >> 5;
    int wm = w & 1, wn = w >> 1;

    wmma::fragment<wmma::accumulator, 16, 16, 8, float> acc[4][2];
#pragma unroll
    for (int mt = 0; mt < 4; mt++)
#pragma unroll
        for (int nt = 0; nt < 2; nt++) wmma::fill_fragment(acc[mt][nt], 0.f);

    for (int kc = 0; kc < K; kc += KC) {
        __syncthreads();
#pragma unroll
        for (int i = tid; i < 1024; i += 256) {
            int r = i >> 3, c = (i & 7) * 4;
            int gm = m0 + r;
            float4 v = (gm < NN) ? *(const float4*)(A + (size_t)gm * K + kc + c)
                                 : make_float4(0.f, 0.f, 0.f, 0.f);
            *(float4*)(&As[r][c]) = v;
        }
#pragma unroll
        for (int i = tid; i < 1024; i += 256) {
            int r = i >> 5, c = (i & 31) * 4;
            float4 v = *(const float4*)(W + (size_t)(kc + r) * COLS + n0 + c);
            *(float4*)(&Ws[r][c]) = v;
        }
        __syncthreads();
#pragma unroll
        for (int k8 = 0; k8 < KC / 8; k8++) {
            wmma::fragment<wmma::matrix_a, 16, 16, 8, wmma::precision::tf32,
                           wmma::row_major> a[4];
#pragma unroll
            for (int mt = 0; mt < 4; mt++) {
                wmma::load_matrix_sync(a[mt], &As[wm * 64 + mt * 16][k8 * 8], 36);
#pragma unroll
                for (int i = 0; i < a[mt].num_elements; i++)
                    a[mt].x[i] = wmma::__float_to_tf32(a[mt].x[i]);
            }
#pragma unroll
            for (int nt = 0; nt < 2; nt++) {
                wmma::fragment<wmma::matrix_b, 16, 16, 8, wmma::precision::tf32,
                               wmma::row_major> b;
                wmma::load_matrix_sync(b, &Ws[k8 * 8][wn * 32 + nt * 16], 132);
#pragma unroll
                for (int i = 0; i < b.num_elements; i++)
                    b.x[i] = wmma::__float_to_tf32(b.x[i]);
#pragma unroll
                for (int mt = 0; mt < 4; mt++)
                    wmma::mma_sync(acc[mt][nt], a[mt], b, acc[mt][nt]);
            }
        }
    }
#pragma unroll
    for (int mt = 0; mt < 4; mt++)
#pragma unroll
        for (int nt = 0; nt < 2; nt++) {
            int gm = m0 + wm * 64 + mt * 16;
            wmma::store_matrix_sync(C + (size_t)gm * COLS + n0 + wn * 32 + nt * 16,
                                    acc[mt][nt], COLS, wmma::mem_row_major);
        }
}

// =================== bf16 GEMM with bf16 output (for P|Q) ====================
template <int K, int COLS>
__global__ __launch_bounds__(256) void k_gemm_bf16o(const float* __restrict__ A,
                                                    const __nv_bfloat16* __restrict__ W,
                                                    __nv_bfloat16* __restrict__ C) {
    constexpr int KC = 32;
    __shared__ __nv_bfloat16 As[128][40];
    __shared__ __nv_bfloat16 Ws[KC][136];
    int m0 = blockIdx.x * 128, n0 = blockIdx.y * 128;
    int tid = threadIdx.x, w = tid >> 5, lane = tid & 31;
    int wm = w & 1, wn = w >> 1;

    wmma::fragment<wmma::accumulator, 16, 16, 16, float> acc[4][2];
#pragma unroll
    for (int mt = 0; mt < 4; mt++)
#pragma unroll
        for (int nt = 0; nt < 2; nt++) wmma::fill_fragment(acc[mt][nt], 0.f);

    for (int kc = 0; kc < K; kc += KC) {
        __syncthreads();
#pragma unroll
        for (int i = tid; i < 1024; i += 256) {
            int r = i >> 3, c = (i & 7) * 4;
            int gm = m0 + r;
            float4 v = (gm < NN) ? *(const float4*)(A + (size_t)gm * K + kc + c)
                                 : make_float4(0.f, 0.f, 0.f, 0.f);
            __nv_bfloat162* dp = (__nv_bfloat162*)(&As[r][c]);
            dp[0] = __floats2bfloat162_rn(v.x, v.y);
            dp[1] = __floats2bfloat162_rn(v.z, v.w);
        }
#pragma unroll
        for (int i = tid; i < 512; i += 256) {
            int r = i >> 4, c = (i & 15) * 8;
            *(uint4*)(&Ws[r][c]) = *(const uint4*)(W + (size_t)(kc + r) * COLS + n0 + c);
        }
        __syncthreads();
#pragma unroll
        for (int k16 = 0; k16 < KC / 16; k16++) {
            wmma::fragment<wmma::matrix_a, 16, 16, 16, __nv_bfloat16, wmma::row_major> a[4];
#pragma unroll
            for (int mt = 0; mt < 4; mt++)
                wmma::load_matrix_sync(a[mt], &As[wm * 64 + mt * 16][k16 * 16], 40);
#pragma unroll
            for (int nt = 0; nt < 2; nt++) {
                wmma::fragment<wmma::matrix_b, 16, 16, 16, __nv_bfloat16, wmma::row_major> b;
                wmma::load_matrix_sync(b, &Ws[k16 * 16][wn * 32 + nt * 16], 136);
#pragma unroll
                for (int mt = 0; mt < 4; mt++)
                    wmma::mma_sync(acc[mt][nt], a[mt], b, acc[mt][nt]);
            }
        }
    }
    __syncthreads();
    float* scratch = (float*)(&As[0][0]) + w * 256;
#pragma unroll
    for (int mt = 0; mt < 4; mt++)
#pragma unroll
        for (int nt = 0; nt < 2; nt++) {
            wmma::store_matrix_sync(scratch, acc[mt][nt], 16, wmma::mem_row_major);
            __syncwarp();
            int row = lane >> 1, colb = (lane & 1) * 8;
            const float* sp = scratch + row * 16 + colb;
            int gm = m0 + wm * 64 + mt * 16 + row;
            __nv_bfloat16* dst = C + (size_t)gm * COLS + n0 + wn * 32 + nt * 16 + colb;
            uint4 o;
            __nv_bfloat162 t;
            t = __floats2bfloat162_rn(sp[0], sp[1]); o.x = *(uint32_t*)&t;
            t = __floats2bfloat162_rn(sp[2], sp[3]); o.y = *(uint32_t*)&t;
            t = __floats2bfloat162_rn(sp[4], sp[5]); o.z = *(uint32_t*)&t;
            t = __floats2bfloat162_rn(sp[6], sp[7]); o.w = *(uint32_t*)&t;
            *(uint4*)dst = o;
            __syncwarp();
        }
}

// ---------------- attention score projections ----------------
template <int H>
__global__ void k_scores(const float* __restrict__ proj, const float* __restrict__ asrc,
                         const float* __restrict__ atrg, float* __restrict__ ssrc,
                         float* __restrict__ strg) {
    int n = blockIdx.x;
    int h = threadIdx.x >> 5, lane = threadIdx.x & 31;
    float4 p = *(const float4*)(proj + ((size_t)n * H + h) * 128 + lane * 4);
    float4 a = *(const float4*)(asrc + h * 128 + lane * 4);
    float4 b = *(const float4*)(atrg + h * 128 + lane * 4);
    float ps = p.x * a.x + p.y * a.y + p.z * a.z + p.w * a.w;
    float pt = p.x * b.x + p.y * b.y + p.z * b.z + p.w * b.w;
#pragma unroll
    for (int o = 16; o > 0; o >>= 1) {
        ps += __shfl_down_sync(0xffffffffu, ps, o);
        pt += __shfl_down_sync(0xffffffffu, pt, o);
    }
    if (lane == 0) { ssrc[n * H + h] = ps; strg[n * H + h] = pt; }
}

// ---------------- merged edge softmax ----------------
template <int H>
__global__ void k_edge_softmax(const int* __restrict__ ei, const float* __restrict__ ss,
                               const float* __restrict__ st, float* __restrict__ eb,
                               float* __restrict__ den) {
    int i = blockIdx.x * blockDim.x + threadIdx.x;
    if (i >= EE) return;
    int s = ei[i], t = ei[EE + i];
#pragma unroll
    for (int h = 0; h < H; h++) {
        float v = ss[s * H + h] + st[t * H + h];
        v = v > 0.f ? v : 0.2f * v;
        float ex = expf(v);
        eb[(size_t)i * H + h] = ex;
        atomicAdd(&den[t * H + h], ex);
    }
}

// ---------------- scatter messages ----------------
template <int H>
__global__ void k_edge_agg(const int* __restrict__ ei, const float* __restrict__ eb,
                           const float* __restrict__ den, const float* __restrict__ proj,
                           float* __restrict__ agg) {
    int g = blockIdx.x * blockDim.x + threadIdx.x;
    int i = g >> 5, lane = g & 31;
    if (i >= EE) return;
    int s = ei[i], t = ei[EE + i];
#pragma unroll
    for (int h = 0; h < H; h++) {
        float att = eb[(size_t)i * H + h] / (den[t * H + h] + 1e-16f);
        float4 p = *(const float4*)(proj + ((size_t)s * H + h) * 128 + lane * 4);
        float* d = agg + ((size_t)t * H + h) * 128 + lane * 4;
        red4(d, p.x * att, p.y * att, p.z * att, p.w * att);
    }
}

__global__ void k_finalize1(const float* __restrict__ local_emb, const float* __restrict__ b1,
                            const float* __restrict__ agg, float* __restrict__ hbuf) {
    int n = blockIdx.x, c = threadIdx.x;
    int h = c >> 8, j = c & 255;
    float v = (j < 128) ? agg[(size_t)n * 256 + h * 128 + j]
                        : local_emb[(size_t)n * 128 + (j - 128)];
    v += b1[c];
    hbuf[(size_t)n * 512 + c] = eluf(v);
}

__global__ void k_finalize2(const float* __restrict__ b2, const float* __restrict__ agg,
                            float* __restrict__ out2) {
    int n = blockIdx.x, f = threadIdx.x;
    const float* a = agg + (size_t)n * 512;
    float v = 0.25f * (a[f] + a[128 + f] + a[256 + f] + a[384 + f]) + b2[f];
    out2[(size_t)n * 128 + f] = eluf(v);
}

// ---------------- MLP weight prep ----------------
__global__ void k_wprep(const float* __restrict__ Wi, __nv_bfloat16* __restrict__ wacad,
                        __nv_bfloat16* __restrict__ wibh) {
    int i = blockIdx.x * blockDim.x + threadIdx.x;
    if (i >= 128 * 2048) return;
    int k = i >> 11, j = i & 2047;
    float v;
    if (j < 1024)
        v = Wi[(size_t)k * 1024 + j] + Wi[(size_t)(256 + k) * 1024 + j];
    else
        v = Wi[(size_t)k * 1024 + (j - 1024)] + Wi[(size_t)(384 + k) * 1024 + (j - 1024)];
    wacad[i] = __float2bfloat16(v);
    if (j < 1024) wibh[(size_t)k * 1024 + j] = __float2bfloat16(Wi[(size_t)(128 + k) * 1024 + j]);
}

__global__ void k_cvt_wf1(const float* __restrict__ Wf1, __nv_bfloat16* __restrict__ out) {
    int i = blockIdx.x * blockDim.x + threadIdx.x;
    if (i < 1024 * 512) out[i] = __float2bfloat16(Wf1[i]);
}

// ============ fused per-edge MLP, bf16 wmma + cp.async pipelined weights =====
// 64 edges/block, 8 warps. Double-buffered wB2 (Wf1 32-row substages) prefetched
// with cp.async during the previous substage's MMA; wB1 for chunk c+1 prefetched
// during chunk c's GEMM2.
#define TE4 64
#define LDA 136
#define LDB2 520
#define LDCF 132
// smem byte offsets
#define M4_MSH 0          // 64*136 bf16 (17408)
#define M4_CH 17408       // 64*136 bf16 (17408), epilogue scratch alias
#define M4_WB1 34816      // 128*136 bf16 (34816)
#define M4_WB2 69632      // 2 x 32*520 bf16 (66560)
#define M4_CHF 136192     // 64*132 f32 (33792)
#define M4_BF1 169984     // 512 f32
#define M4_WF2 172032     // 512 f32
#define M4_PART 174080    // 64 f32
#define M4_SIDX 174336    // 64 int
#define M4_TIDX 174592    // 64 int
#define M4_TOTAL 174848

typedef wmma::fragment<wmma::matrix_a, 16, 16, 16, __nv_bfloat16, wmma::row_major> FragA;
typedef wmma::fragment<wmma::matrix_b, 16, 16, 16, __nv_bfloat16, wmma::row_major> FragB;
typedef wmma::fragment<wmma::accumulator, 16, 16, 16, float> FragC;

__global__ __launch_bounds__(256, 1) void k_edge_mlp4(
    const int* __restrict__ ei, const float* __restrict__ out2,
    const __nv_bfloat16* __restrict__ PQh,
    const __nv_bfloat16* __restrict__ WibH, const float* __restrict__ bi,
    const __nv_bfloat16* __restrict__ Wf1H, const float* __restrict__ bf1,
    const float* __restrict__ Wf2, const float* __restrict__ bf2,
    float* __restrict__ outp) {
    extern __shared__ char sm[];
    __nv_bfloat16* msh = (__nv_bfloat16*)(sm + M4_MSH);
    __nv_bfloat16* ch = (__nv_bfloat16*)(sm + M4_CH);
    __nv_bfloat16* wB1 = (__nv_bfloat16*)(sm + M4_WB1);
    float* chf = (float*)(sm + M4_CHF);
    float* bf1s = (float*)(sm + M4_BF1);
    float* wf2s = (float*)(sm + M4_WF2);
    float* partial = (float*)(sm + M4_PART);
    int* sidx = (int*)(sm + M4_SIDX);
    int* tidx = (int*)(sm + M4_TIDX);
    float* scr = (float*)ch;

    uint32_t smb = smem_u32(sm);
    int tid = threadIdx.x, w = tid >> 5, lane = tid & 31;
    int e0 = blockIdx.x * TE4;

    // ---- cp.async stagers ----
    auto stage_wb1 = [&](int c) {
        const uint4* src = (const uint4*)(WibH) + ((c << 7) >> 3);
        uint32_t dstb = smb + M4_WB1;
#pragma unroll
        for (int i = tid; i < 2048; i += 256) {
            int r = i >> 4, cc = i & 15;
            cpa16(dstb + (uint32_t)(r * 17 + cc) * 16, src + (size_t)r * 128 + cc);
        }
    };
    auto stage_wb2 = [&](int stage) {  // stage = c*4 + ks, buffer = stage & 1
        int c = stage >> 2, ks = stage & 3;
        const uint4* src = (const uint4*)(Wf1H + (size_t)((c << 7) + ks * 32) * 512);
        uint32_t dstb = smb + M4_WB2 + (uint32_t)(stage & 1) * 33280u;
#pragma unroll
        for (int i = tid; i < 2048; i += 256) {
            int r = i >> 6, cc = i & 63;
            cpa16(dstb + (uint32_t)(r * 65 + cc) * 16, src + (size_t)r * 64 + cc);
        }
    };

    if (tid < TE4) {
        sidx[tid] = ei[e0 + tid];
        tidx[tid] = ei[EE + e0 + tid];
        partial[tid] = 0.f;
    }
    for (int i = tid; i < 512; i += 256) { bf1s[i] = bf1[i]; wf2s[i] = Wf2[i]; }

    // prologue prefetch: wB1(0), wB2(stage 0)
    stage_wb1(0); CP_COMMIT();
    stage_wb2(0); CP_COMMIT();
    __syncthreads();  // sidx visible

    // msh = bf16(e1 * e2)
    for (int idx = tid; idx < TE4 * 32; idx += 256) {
        int e = idx >> 5, j = (idx & 31) * 4;
        float4 a = *(const float4*)(out2 + (size_t)sidx[e] * 128 + j);
        float4 b = *(const float4*)(out2 + (size_t)tidx[e] * 128 + j);
        __nv_bfloat162* mp = (__nv_bfloat162*)(msh + e * LDA + j);
        mp[0] = __floats2bfloat162_rn(a.x * b.x, a.y * b.y);
        mp[1] = __floats2bfloat162_rn(a.z * b.z, a.w * b.w);
    }

    FragC hacc[4][4];
#pragma unroll
    for (int mt = 0; mt < 4; mt++)
#pragma unroll
        for (int nt = 0; nt < 4; nt++) wmma::fill_fragment(hacc[mt][nt], 0.f);

    const int mt1 = w & 3;
    const int nb1 = (w >> 2) * 4;

    for (int c = 0; c < 8; c++) {
        int jb = c << 7;
        CP_WAIT0();
        __syncthreads();  // wB1(c) ready; msh ready (c=0); prev chunk MMA fully done

        // ---- GEMM1: acc1 = msh @ wB1 ----
        FragC acc1[4];
#pragma unroll
        for (int nt = 0; nt < 4; nt++) wmma::fill_fragment(acc1[nt], 0.f);
#pragma unroll
        for (int k0 = 0; k0 < 8; k0++) {
            FragA a;
            wmma::load_matrix_sync(a, msh + (mt1 * 16) * LDA + k0 * 16, LDA);
#pragma unroll
            for (int nt = 0; nt < 4; nt++) {
                FragB b;
                wmma::load_matrix_sync(b, wB1 + (k0 * 16) * LDA + (nb1 + nt) * 16, LDA);
                wmma::mma_sync(acc1[nt], a, b, acc1[nt]);
            }
        }
#pragma unroll
        for (int nt = 0; nt < 4; nt++)
            wmma::store_matrix_sync(chf + (mt1 * 16) * LDCF + (nb1 + nt) * 16, acc1[nt],
                                    LDCF, wmma::mem_row_major);
        __syncthreads();  // all GEMM1 reads of wB1 done; chf visible

        // prefetch next chunk's wB1 during GEMM2 phase
        if (c < 7) { stage_wb1(c + 1); CP_COMMIT(); }

        // ---- elementwise: ch = bf16(relu(chf + P[s] + Q[t] + bi)) ----
        for (int idx = tid; idx < TE4 * 32; idx += 256) {
            int e = idx >> 5, j = (idx & 31) * 4;
            float4 v = *(float4*)(chf + e * LDCF + j);
            uint2 pu = *(const uint2*)(PQh + (size_t)sidx[e] * 2048 + jb + j);
            uint2 qu = *(const uint2*)(PQh + (size_t)tidx[e] * 2048 + 1024 + jb + j);
            float4 bv = *(const float4*)(bi + jb + j);
            float2 p01 = __bfloat1622float2(*(__nv_bfloat162*)&pu.x);
            float2 p23 = __bfloat1622float2(*(__nv_bfloat162*)&pu.y);
            float2 q01 = __bfloat1622float2(*(__nv_bfloat162*)&qu.x);
            float2 q23 = __bfloat1622float2(*(__nv_bfloat162*)&qu.y);
            float r0 = fmaxf(v.x + p01.x + q01.x + bv.x, 0.f);
            float r1 = fmaxf(v.y + p01.y + q01.y + bv.y, 0.f);
            float r2 = fmaxf(v.z + p23.x + q23.x + bv.z, 0.f);
            float r3 = fmaxf(v.w + p23.y + q23.y + bv.w, 0.f);
            __nv_bfloat162* cp = (__nv_bfloat162*)(ch + e * LDA + j);
            cp[0] = __floats2bfloat162_rn(r0, r1);
            cp[1] = __floats2bfloat162_rn(r2, r3);
        }
        __syncthreads();  // ch visible

        // ---- GEMM2: hacc += ch @ Wf1[jb:jb+128, :], 4 pipelined substages ----
        for (int ks = 0; ks < 4; ks++) {
            int stage = c * 4 + ks;
            CP_WAIT0();
            __syncthreads();  // wB2(stage) ready; all warps done with mma(stage-1)
            if (stage < 31) { stage_wb2(stage + 1); CP_COMMIT(); }  // overlaps this mma
            const __nv_bfloat16* wB2p =
                (const __nv_bfloat16*)(sm + M4_WB2 + (stage & 1) * 33280);
#pragma unroll
            for (int k2 = 0; k2 < 2; k2++) {
                FragA a[4];
#pragma unroll
                for (int mt = 0; mt < 4; mt++)
                    wmma::load_matrix_sync(a[mt], ch + (mt * 16) * LDA + ks * 32 + k2 * 16, LDA);
#pragma unroll
                for (int nt = 0; nt < 4; nt++) {
                    FragB b;
                    wmma::load_matrix_sync(b, wB2p + (k2 * 16) * LDB2 + w * 64 + nt * 16, LDB2);
#pragma unroll
                    for (int mt = 0; mt < 4; mt++)
                        wmma::mma_sync(hacc[mt][nt], a[mt], b, hacc[mt][nt]);
                }
            }
        }
    }
    __syncthreads();

    // ---- epilogue ----
    float* myscr = scr + w * 256;
#pragma unroll
    for (int mt = 0; mt < 4; mt++) {
#pragma unroll
        for (int nt = 0; nt < 4; nt++) {
            wmma::store_matrix_sync(myscr, hacc[mt][nt], 16, wmma::mem_row_major);
            __syncwarp();
            int r = lane & 15, cc0 = (lane >> 4) * 8;
            int n0 = w * 64 + nt * 16 + cc0;
            float s = 0.f;
#pragma unroll
            for (int cc = 0; cc < 8; cc++) {
                float v = myscr[r * 16 + cc0 + cc];
                int n = n0 + cc;
                s += fmaxf(v + bf1s[n], 0.f) * wf2s[n];
            }
            atomicAdd(&partial[mt * 16 + r], s);
            __syncwarp();
        }
    }
    __syncthreads();
    if (tid < TE4) {
        float lg = partial[tid] + bf2[0];
        outp[e0 + tid] = 1.f / (1.f + expf(-lg));
    }
}

// ---------------- launch ----------------
extern "C" void kernel_launch(void* const* d_in, const int* in_sizes, int n_in,
                              void* d_out, int out_size) {
    const float* x = (const float*)d_in[0];
    const int* ei = (const int*)d_in[1];
    const float* local_emb = (const float*)d_in[2];
    const float* W1 = (const float*)d_in[3];
    const float* a_src1 = (const float*)d_in[4];
    const float* a_trg1 = (const float*)d_in[5];
    const float* b1 = (const float*)d_in[6];
    const float* W2 = (const float*)d_in[7];
    const float* a_src2 = (const float*)d_in[8];
    const float* a_trg2 = (const float*)d_in[9];
    const float* b2 = (const float*)d_in[10];
    const float* Wi = (const float*)d_in[11];
    const float* bi = (const float*)d_in[12];
    const float* Wf1 = (const float*)d_in[13];
    const float* bf1 = (const float*)d_in[14];
    const float* Wf2 = (const float*)d_in[15];
    const float* bf2 = (const float*)d_in[16];
    float* outp = (float*)d_out;

    void* tmp;
    float *p_proj1, *p_ssrc1, *p_strg1, *p_e1, *p_den1, *p_agg1, *p_h;
    float *p_proj2, *p_ssrc2, *p_strg2, *p_e2, *p_den2, *p_agg2, *p_out2;
    __nv_bfloat16 *p_PQh, *p_wacad, *p_wibh, *p_wf1h;
#define SYM(p, s) cudaGetSymbolAddress(&tmp, s); p = (decltype(p))tmp;
    SYM(p_proj1, g_proj1) SYM(p_ssrc1, g_ssrc1) SYM(p_strg1, g_strg1)
    SYM(p_e1, g_e1) SYM(p_den1, g_den1) SYM(p_agg1, g_agg1) SYM(p_h, g_h)
    SYM(p_proj2, g_proj2) SYM(p_ssrc2, g_ssrc2) SYM(p_strg2, g_strg2)
    SYM(p_e2, g_e2) SYM(p_den2, g_den2) SYM(p_agg2, g_agg2) SYM(p_out2, g_out2)
    SYM(p_PQh, g_PQh) SYM(p_wacad, g_wacad) SYM(p_wibh, g_wib_h) SYM(p_wf1h, g_wf1_h)
#undef SYM

    const int EB = (EE + 255) / 256;
    cudaFuncSetAttribute(k_edge_mlp4, cudaFuncAttributeMaxDynamicSharedMemorySize, M4_TOTAL);

    k_init<<<256, 256>>>();
    k_wprep<<<1024, 256>>>(Wi, p_wacad, p_wibh);
    k_cvt_wf1<<<2048, 256>>>(Wf1, p_wf1h);

    // ---- GAT layer 1 ----
    k_gemm_tf32<128, 256><<<dim3(NP / 128, 2), 256>>>(x, W1, p_proj1);
    k_scores<2><<<NN, 64>>>(p_proj1, a_src1, a_trg1, p_ssrc1, p_strg1);
    k_edge_softmax<2><<<EB, 256>>>(ei, p_ssrc1, p_strg1, p_e1, p_den1);
    k_edge_agg<2><<<EE / 8, 256>>>(ei, p_e1, p_den1, p_proj1, p_agg1);
    k_finalize1<<<NN, 512>>>(local_emb, b1, p_agg1, p_h);

    // ---- GAT layer 2 ----
    k_gemm_tf32<512, 512><<<dim3(NP / 128, 4), 256>>>(p_h, W2, p_proj2);
    k_scores<4><<<NN, 128>>>(p_proj2, a_src2, a_trg2, p_ssrc2, p_strg2);
    k_edge_softmax<4><<<EB, 256>>>(ei, p_ssrc2, p_strg2, p_e2, p_den2);
    k_edge_agg<4><<<EE / 8, 256>>>(ei, p_e2, p_den2, p_proj2, p_agg2);
    k_finalize2<<<NN, 128>>>(b2, p_agg2, p_out2);

    // ---- P|Q combined bf16 GEMM (bf16 output) ----
    k_gemm_bf16o<128, 2048><<<dim3(NP / 128, 16), 256>>>(p_out2, p_wacad, p_PQh);

    // ---- fused edge MLP (pipelined bf16 wmma) ----
    k_edge_mlp4<<<EE / TE4, 256, M4_TOTAL>>>(ei, p_out2, p_PQh, p_wibh, bi, p_wf1h,
                                             bf1, Wf2, bf2, outp);
}

// round 9
// speedup vs baseline: 4.8235x; 1.0399x over previous
#include <cuda_runtime.h>
#include <cuda_bf16.h>
#include <mma.h>
#include <math.h>
#include <cstdint>

using namespace nvcuda;

#define NN 10000
#define NP 10112
#define EE 160000

// ---------------- device scratch ----------------
__device__ float g_proj1[NP * 256];
__device__ float g_ssrc1[NN * 2];
__device__ float g_strg1[NN * 2];
__device__ float g_e1[EE * 2];
__device__ float g_den1[NN * 2];
__device__ float g_agg1[NN * 256];
__device__ float g_h[NP * 512];
__device__ float g_proj2[NP * 512];
__device__ float g_ssrc2[NN * 4];
__device__ float g_strg2[NN * 4];
__device__ float g_e2[EE * 4];
__device__ float g_den2[NN * 4];
__device__ float g_agg2[NN * 512];
__device__ float g_out2[NP * 128];
__device__ __nv_bfloat16 g_out2h[NP * 128];       // bf16 copy of out2
__device__ __nv_bfloat16 g_PQh[NP * 2048];        // bf16 [P | Q]
__device__ __nv_bfloat16 g_wacad[128 * 2048];     // [Wi_a+Wi_c | Wi_a+Wi_d] bf16
__device__ __nv_bfloat16 g_wib_h[128 * 1024];     // Wi rows 128..255, bf16
__device__ __nv_bfloat16 g_wf1_h[1024 * 512];     // Wf1 bf16

__device__ __forceinline__ float eluf(float v) { return v > 0.f ? v : expm1f(v); }

__device__ __forceinline__ void red4(float* p, float a, float b, float c, float d) {
    asm volatile("red.global.add.v4.f32 [%0], {%1,%2,%3,%4};"
                 :: "l"(p), "f"(a), "f"(b), "f"(c), "f"(d) : "memory");
}

__device__ __forceinline__ uint32_t smem_u32(const void* p) {
    uint32_t a;
    asm("{ .reg .u64 t; cvta.to.shared.u64 t, %1; cvt.u32.u64 %0, t; }" : "=r"(a) : "l"(p));
    return a;
}
__device__ __forceinline__ void cpa16(uint32_t saddr, const void* g) {
    asm volatile("cp.async.cg.shared.global [%0], [%1], 16;" :: "r"(saddr), "l"(g));
}
__device__ __forceinline__ void cpa16p(uint32_t saddr, const void* g, bool pred) {
    int sz = pred ? 16 : 0;
    asm volatile("cp.async.cg.shared.global [%0], [%1], 16, %2;"
                 :: "r"(saddr), "l"(g), "r"(sz));
}
#define CP_COMMIT() asm volatile("cp.async.commit_group;" ::: "memory")
#define CP_WAIT0()  asm volatile("cp.async.wait_group 0;" ::: "memory")
#define CP_WAIT1()  asm volatile("cp.async.wait_group 1;" ::: "memory")

// ---------------- init ----------------
__global__ void k_init() {
    int i = blockIdx.x * blockDim.x + threadIdx.x;
    int stride = gridDim.x * blockDim.x;
    for (int j = i; j < NN * 256; j += stride) g_agg1[j] = 0.f;
    for (int j = i; j < NN * 512; j += stride) g_agg2[j] = 0.f;
    for (int j = i; j < NN * 2; j += stride) g_den1[j] = 0.f;
    for (int j = i; j < NN * 4; j += stride) g_den2[j] = 0.f;
}

// =================== tf32 GEMM v2: cp.async double-buffered, no cvt loops ====
// (tf32 HMMA truncates low mantissa bits of raw fp32 fragments itself.)
template <int K, int COLS>
__global__ __launch_bounds__(256) void k_gemm_tf32(const float* __restrict__ A,
                                                   const float* __restrict__ W,
                                                   float* __restrict__ C) {
    constexpr int KC = 32;
    constexpr int NSTG = K / KC;
    extern __shared__ float smf[];
    float* As = smf;                   // [2][128][36]
    float* Ws = smf + 2 * 128 * 36;    // [2][32][132]
    uint32_t asb = smem_u32(As), wsb = smem_u32(Ws);
    int m0 = blockIdx.x * 128, n0 = blockIdx.y * 128;
    int tid = threadIdx.x, w = tid >> 5;
    int wm = w & 1, wn = w >> 1;

    auto stage = [&](int s) {
        int kc = s * KC, buf = s & 1;
#pragma unroll
        for (int i = tid; i < 1024; i += 256) {
            int r = i >> 3, c = (i & 7) * 4;
            int gm = m0 + r;
            const float* src = (gm < NN) ? (A + (size_t)gm * K + kc + c) : A;
            cpa16p(asb + (uint32_t)((buf * 128 + r) * 36 + c) * 4, src, gm < NN);
        }
#pragma unroll
        for (int i = tid; i < 1024; i += 256) {
            int r = i >> 5, c = (i & 31) * 4;
            cpa16(wsb + (uint32_t)((buf * 32 + r) * 132 + c) * 4,
                  W + (size_t)(kc + r) * COLS + n0 + c);
        }
    };

    wmma::fragment<wmma::accumulator, 16, 16, 8, float> acc[4][2];
#pragma unroll
    for (int mt = 0; mt < 4; mt++)
#pragma unroll
        for (int nt = 0; nt < 2; nt++) wmma::fill_fragment(acc[mt][nt], 0.f);

    stage(0); CP_COMMIT();
    for (int s = 0; s < NSTG; s++) {
        if (s + 1 < NSTG) { stage(s + 1); CP_COMMIT(); CP_WAIT1(); }
        else { CP_WAIT0(); }
        __syncthreads();
        const float* Ab = As + (s & 1) * 128 * 36;
        const float* Wb = Ws + (s & 1) * 32 * 132;
#pragma unroll
        for (int k8 = 0; k8 < KC / 8; k8++) {
            wmma::fragment<wmma::matrix_a, 16, 16, 8, wmma::precision::tf32,
                           wmma::row_major> a[4];
#pragma unroll
            for (int mt = 0; mt < 4; mt++)
                wmma::load_matrix_sync(a[mt], Ab + (wm * 64 + mt * 16) * 36 + k8 * 8, 36);
#pragma unroll
            for (int nt = 0; nt < 2; nt++) {
                wmma::fragment<wmma::matrix_b, 16, 16, 8, wmma::precision::tf32,
                               wmma::row_major> b;
                wmma::load_matrix_sync(b, Wb + (k8 * 8) * 132 + wn * 32 + nt * 16, 132);
#pragma unroll
                for (int mt = 0; mt < 4; mt++)
                    wmma::mma_sync(acc[mt][nt], a[mt], b, acc[mt][nt]);
            }
        }
        __syncthreads();
    }
#pragma unroll
    for (int mt = 0; mt < 4; mt++)
#pragma unroll
        for (int nt = 0; nt < 2; nt++) {
            int gm = m0 + wm * 64 + mt * 16;
            wmma::store_matrix_sync(C + (size_t)gm * COLS + n0 + wn * 32 + nt * 16,
                                    acc[mt][nt], COLS, wmma::mem_row_major);
        }
}
#define TF32_SMEM ((2 * 128 * 36 + 2 * 32 * 132) * 4)

// ====== bf16 GEMM v2 (A bf16, W bf16, C bf16) — cp.async double-buffered =====
template <int K, int COLS>
__global__ __launch_bounds__(256) void k_gemm_bf16h(const __nv_bfloat16* __restrict__ A,
                                                    const __nv_bfloat16* __restrict__ W,
                                                    __nv_bfloat16* __restrict__ C) {
    constexpr int KC = 32;
    constexpr int NSTG = K / KC;
    __shared__ __nv_bfloat16 As[2][128][40];
    __shared__ __nv_bfloat16 Ws[2][KC][136];
    uint32_t asb = smem_u32(&As[0][0][0]), wsb = smem_u32(&Ws[0][0][0]);
    int m0 = blockIdx.x * 128, n0 = blockIdx.y * 128;
    int tid = threadIdx.x, w = tid >> 5, lane = tid & 31;
    int wm = w & 1, wn = w >> 1;

    auto stage = [&](int s) {
        int kc = s * KC, buf = s & 1;
#pragma unroll
        for (int i = tid; i < 512; i += 256) {
            int r = i >> 2, c = (i & 3) * 8;
            cpa16(asb + (uint32_t)((buf * 128 + r) * 40 + c) * 2,
                  A + (size_t)(m0 + r) * K + kc + c);
        }
#pragma unroll
        for (int i = tid; i < 512; i += 256) {
            int r = i >> 4, c = (i & 15) * 8;
            cpa16(wsb + (uint32_t)((buf * KC + r) * 136 + c) * 2,
                  W + (size_t)(kc + r) * COLS + n0 + c);
        }
    };

    wmma::fragment<wmma::accumulator, 16, 16, 16, float> acc[4][2];
#pragma unroll
    for (int mt = 0; mt < 4; mt++)
#pragma unroll
        for (int nt = 0; nt < 2; nt++) wmma::fill_fragment(acc[mt][nt], 0.f);

    stage(0); CP_COMMIT();
    for (int s = 0; s < NSTG; s++) {
        if (s + 1 < NSTG) { stage(s + 1); CP_COMMIT(); CP_WAIT1(); }
        else { CP_WAIT0(); }
        __syncthreads();
        const __nv_bfloat16* Ab = &As[s & 1][0][0];
        const __nv_bfloat16* Wb = &Ws[s & 1][0][0];
#pragma unroll
        for (int k16 = 0; k16 < KC / 16; k16++) {
            wmma::fragment<wmma::matrix_a, 16, 16, 16, __nv_bfloat16, wmma::row_major> a[4];
#pragma unroll
            for (int mt = 0; mt < 4; mt++)
                wmma::load_matrix_sync(a[mt], Ab + (wm * 64 + mt * 16) * 40 + k16 * 16, 40);
#pragma unroll
            for (int nt = 0; nt < 2; nt++) {
                wmma::fragment<wmma::matrix_b, 16, 16, 16, __nv_bfloat16, wmma::row_major> b;
                wmma::load_matrix_sync(b, Wb + (k16 * 16) * 136 + wn * 32 + nt * 16, 136);
#pragma unroll
                for (int mt = 0; mt < 4; mt++)
                    wmma::mma_sync(acc[mt][nt], a[mt], b, acc[mt][nt]);
            }
        }
        __syncthreads();
    }
    float* scratch = (float*)(&As[0][0][0]) + w * 256;
#pragma unroll
    for (int mt = 0; mt < 4; mt++)
#pragma unroll
        for (int nt = 0; nt < 2; nt++) {
            wmma::store_matrix_sync(scratch, acc[mt][nt], 16, wmma::mem_row_major);
            __syncwarp();
            int row = lane >> 1, colb = (lane & 1) * 8;
            const float* sp = scratch + row * 16 + colb;
            int gm = m0 + wm * 64 + mt * 16 + row;
            __nv_bfloat16* dst = C + (size_t)gm * COLS + n0 + wn * 32 + nt * 16 + colb;
            uint4 o;
            __nv_bfloat162 t;
            t = __floats2bfloat162_rn(sp[0], sp[1]); o.x = *(uint32_t*)&t;
            t = __floats2bfloat162_rn(sp[2], sp[3]); o.y = *(uint32_t*)&t;
            t = __floats2bfloat162_rn(sp[4], sp[5]); o.z = *(uint32_t*)&t;
            t = __floats2bfloat162_rn(sp[6], sp[7]); o.w = *(uint32_t*)&t;
            *(uint4*)dst = o;
            __syncwarp();
        }
}

// ---------------- attention score projections ----------------
template <int H>
__global__ void k_scores(const float* __restrict__ proj, const float* __restrict__ asrc,
                         const float* __restrict__ atrg, float* __restrict__ ssrc,
                         float* __restrict__ strg) {
    int n = blockIdx.x;
    int h = threadIdx.x >> 5, lane = threadIdx.x & 31;
    float4 p = *(const float4*)(proj + ((size_t)n * H + h) * 128 + lane * 4);
    float4 a = *(const float4*)(asrc + h * 128 + lane * 4);
    float4 b = *(const float4*)(atrg + h * 128 + lane * 4);
    float ps = p.x * a.x + p.y * a.y + p.z * a.z + p.w * a.w;
    float pt = p.x * b.x + p.y * b.y + p.z * b.z + p.w * b.w;
#pragma unroll
    for (int o = 16; o > 0; o >>= 1) {
        ps += __shfl_down_sync(0xffffffffu, ps, o);
        pt += __shfl_down_sync(0xffffffffu, pt, o);
    }
    if (lane == 0) { ssrc[n * H + h] = ps; strg[n * H + h] = pt; }
}

// ---------------- merged edge softmax ----------------
template <int H>
__global__ void k_edge_softmax(const int* __restrict__ ei, const float* __restrict__ ss,
                               const float* __restrict__ st, float* __restrict__ eb,
                               float* __restrict__ den) {
    int i = blockIdx.x * blockDim.x + threadIdx.x;
    if (i >= EE) return;
    int s = ei[i], t = ei[EE + i];
#pragma unroll
    for (int h = 0; h < H; h++) {
        float v = ss[s * H + h] + st[t * H + h];
        v = v > 0.f ? v : 0.2f * v;
        float ex = expf(v);
        eb[(size_t)i * H + h] = ex;
        atomicAdd(&den[t * H + h], ex);
    }
}

// ---------------- scatter messages ----------------
template <int H>
__global__ void k_edge_agg(const int* __restrict__ ei, const float* __restrict__ eb,
                           const float* __restrict__ den, const float* __restrict__ proj,
                           float* __restrict__ agg) {
    int g = blockIdx.x * blockDim.x + threadIdx.x;
    int i = g >> 5, lane = g & 31;
    if (i >= EE) return;
    int s = ei[i], t = ei[EE + i];
#pragma unroll
    for (int h = 0; h < H; h++) {
        float att = eb[(size_t)i * H + h] / (den[t * H + h] + 1e-16f);
        float4 p = *(const float4*)(proj + ((size_t)s * H + h) * 128 + lane * 4);
        float* d = agg + ((size_t)t * H + h) * 128 + lane * 4;
        red4(d, p.x * att, p.y * att, p.z * att, p.w * att);
    }
}

__global__ void k_finalize1(const float* __restrict__ local_emb, const float* __restrict__ b1,
                            const float* __restrict__ agg, float* __restrict__ hbuf) {
    int n = blockIdx.x, c = threadIdx.x;
    int h = c >> 8, j = c & 255;
    float v = (j < 128) ? agg[(size_t)n * 256 + h * 128 + j]
                        : local_emb[(size_t)n * 128 + (j - 128)];
    v += b1[c];
    hbuf[(size_t)n * 512 + c] = eluf(v);
}

__global__ void k_finalize2(const float* __restrict__ b2, const float* __restrict__ agg,
                            float* __restrict__ out2, __nv_bfloat16* __restrict__ out2h) {
    int n = blockIdx.x, f = threadIdx.x;
    const float* a = agg + (size_t)n * 512;
    float v = 0.25f * (a[f] + a[128 + f] + a[256 + f] + a[384 + f]) + b2[f];
    v = eluf(v);
    out2[(size_t)n * 128 + f] = v;
    out2h[(size_t)n * 128 + f] = __float2bfloat16(v);
}

// ---------------- MLP weight prep ----------------
__global__ void k_wprep(const float* __restrict__ Wi, __nv_bfloat16* __restrict__ wacad,
                        __nv_bfloat16* __restrict__ wibh) {
    int i = blockIdx.x * blockDim.x + threadIdx.x;
    if (i >= 128 * 2048) return;
    int k = i >> 11, j = i & 2047;
    float v;
    if (j < 1024)
        v = Wi[(size_t)k * 1024 + j] + Wi[(size_t)(256 + k) * 1024 + j];
    else
        v = Wi[(size_t)k * 1024 + (j - 1024)] + Wi[(size_t)(384 + k) * 1024 + (j - 1024)];
    wacad[i] = __float2bfloat16(v);
    if (j < 1024) wibh[(size_t)k * 1024 + j] = __float2bfloat16(Wi[(size_t)(128 + k) * 1024 + j]);
}

__global__ void k_cvt_wf1(const float* __restrict__ Wf1, __nv_bfloat16* __restrict__ out) {
    int i = blockIdx.x * blockDim.x + threadIdx.x;
    if (i < 1024 * 512) out[i] = __float2bfloat16(Wf1[i]);
}

// ============ fused per-edge MLP v2: per-warp elementwise, pipelined =========
#define TE4 64
#define LDA 136
#define LDB2 520
// smem byte offsets
#define M4_MSH 0          // 64*136 bf16 (17408)
#define M4_CH 17408       // 64*136 bf16 (17408)
#define M4_WB1 34816      // 128*136 bf16 (34816)
#define M4_WB2 69632      // 2 x 32*520 bf16 (66560)
#define M4_SCR 136192     // 8*256 f32 (8192)
#define M4_BF1 144384     // 512 f32
#define M4_WF2 146432     // 512 f32
#define M4_PART 148480    // 64 f32
#define M4_SIDX 148736    // 64 int
#define M4_TIDX 148992    // 64 int
#define M4_TOTAL 149248

typedef wmma::fragment<wmma::matrix_a, 16, 16, 16, __nv_bfloat16, wmma::row_major> FragA;
typedef wmma::fragment<wmma::matrix_b, 16, 16, 16, __nv_bfloat16, wmma::row_major> FragB;
typedef wmma::fragment<wmma::accumulator, 16, 16, 16, float> FragC;

__global__ __launch_bounds__(256, 1) void k_edge_mlp4(
    const int* __restrict__ ei, const float* __restrict__ out2,
    const __nv_bfloat16* __restrict__ PQh,
    const __nv_bfloat16* __restrict__ WibH, const float* __restrict__ bi,
    const __nv_bfloat16* __restrict__ Wf1H, const float* __restrict__ bf1,
    const float* __restrict__ Wf2, const float* __restrict__ bf2,
    float* __restrict__ outp) {
    extern __shared__ char sm[];
    __nv_bfloat16* msh = (__nv_bfloat16*)(sm + M4_MSH);
    __nv_bfloat16* ch = (__nv_bfloat16*)(sm + M4_CH);
    __nv_bfloat16* wB1 = (__nv_bfloat16*)(sm + M4_WB1);
    float* bf1s = (float*)(sm + M4_BF1);
    float* wf2s = (float*)(sm + M4_WF2);
    float* partial = (float*)(sm + M4_PART);
    int* sidx = (int*)(sm + M4_SIDX);
    int* tidx = (int*)(sm + M4_TIDX);
    float* scr = (float*)(sm + M4_SCR);

    uint32_t smb = smem_u32(sm);
    int tid = threadIdx.x, w = tid >> 5, lane = tid & 31;
    int e0 = blockIdx.x * TE4;

    auto stage_wb1 = [&](int c) {
        const uint4* src = (const uint4*)(WibH) + ((c << 7) >> 3);
        uint32_t dstb = smb + M4_WB1;
#pragma unroll
        for (int i = tid; i < 2048; i += 256) {
            int r = i >> 4, cc = i & 15;
            cpa16(dstb + (uint32_t)(r * 17 + cc) * 16, src + (size_t)r * 128 + cc);
        }
    };
    auto stage_wb2 = [&](int stage) {
        int c = stage >> 2, ks = stage & 3;
        const uint4* src = (const uint4*)(Wf1H + (size_t)((c << 7) + ks * 32) * 512);
        uint32_t dstb = smb + M4_WB2 + (uint32_t)(stage & 1) * 33280u;
#pragma unroll
        for (int i = tid; i < 2048; i += 256) {
            int r = i >> 6, cc = i & 63;
            cpa16(dstb + (uint32_t)(r * 65 + cc) * 16, src + (size_t)r * 64 + cc);
        }
    };

    if (tid < TE4) {
        sidx[tid] = ei[e0 + tid];
        tidx[tid] = ei[EE + e0 + tid];
        partial[tid] = 0.f;
    }
    for (int i = tid; i < 512; i += 256) { bf1s[i] = bf1[i]; wf2s[i] = Wf2[i]; }

    stage_wb1(0); CP_COMMIT();
    stage_wb2(0); CP_COMMIT();
    __syncthreads();  // sidx visible

    // msh = bf16(e1 * e2)
    for (int idx = tid; idx < TE4 * 32; idx += 256) {
        int e = idx >> 5, j = (idx & 31) * 4;
        float4 a = *(const float4*)(out2 + (size_t)sidx[e] * 128 + j);
        float4 b = *(const float4*)(out2 + (size_t)tidx[e] * 128 + j);
        __nv_bfloat162* mp = (__nv_bfloat162*)(msh + e * LDA + j);
        mp[0] = __floats2bfloat162_rn(a.x * b.x, a.y * b.y);
        mp[1] = __floats2bfloat162_rn(a.z * b.z, a.w * b.w);
    }

    FragC hacc[4][4];
#pragma unroll
    for (int mt = 0; mt < 4; mt++)
#pragma unroll
        for (int nt = 0; nt < 4; nt++) wmma::fill_fragment(hacc[mt][nt], 0.f);

    const int mt1 = w & 3;           // row group (16 rows)
    const int cb1 = (w >> 2) * 64;   // col base within chunk

    for (int c = 0; c < 8; c++) {
        int jb = c << 7;
        CP_WAIT0();
        __syncthreads();  // wB1(c) ready; prev chunk fully done

        // ---- GEMM1: acc1 = msh @ wB1, warp tile 16 rows x 64 cols ----
        FragC acc1[4];
#pragma unroll
        for (int nt = 0; nt < 4; nt++) wmma::fill_fragment(acc1[nt], 0.f);
#pragma unroll
        for (int k0 = 0; k0 < 8; k0++) {
            FragA a;
            wmma::load_matrix_sync(a, msh + (mt1 * 16) * LDA + k0 * 16, LDA);
#pragma unroll
            for (int nt = 0; nt < 4; nt++) {
                FragB b;
                wmma::load_matrix_sync(b, wB1 + (k0 * 16) * LDA + cb1 + nt * 16, LDA);
                wmma::mma_sync(acc1[nt], a, b, acc1[nt]);
            }
        }
        // ---- per-warp elementwise: ch = bf16(relu(acc1 + P + Q + bi)) ----
        {
            float* wscr = scr + w * 256;
            int r = lane >> 1, cb = (lane & 1) * 8;
#pragma unroll
            for (int nt = 0; nt < 4; nt++) {
                wmma::store_matrix_sync(wscr, acc1[nt], 16, wmma::mem_row_major);
                __syncwarp();
                int e = mt1 * 16 + r;
                int jc = cb1 + nt * 16 + cb;
                float4 v0 = *(float4*)(wscr + r * 16 + cb);
                float4 v1 = *(float4*)(wscr + r * 16 + cb + 4);
                uint4 pu = *(const uint4*)(PQh + (size_t)sidx[e] * 2048 + jb + jc);
                uint4 qu = *(const uint4*)(PQh + (size_t)tidx[e] * 2048 + 1024 + jb + jc);
                float4 bi0 = *(const float4*)(bi + jb + jc);
                float4 bi1 = *(const float4*)(bi + jb + jc + 4);
                float2 p01 = __bfloat1622float2(*(__nv_bfloat162*)&pu.x);
                float2 p23 = __bfloat1622float2(*(__nv_bfloat162*)&pu.y);
                float2 p45 = __bfloat1622float2(*(__nv_bfloat162*)&pu.z);
                float2 p67 = __bfloat1622float2(*(__nv_bfloat162*)&pu.w);
                float2 q01 = __bfloat1622float2(*(__nv_bfloat162*)&qu.x);
                float2 q23 = __bfloat1622float2(*(__nv_bfloat162*)&qu.y);
                float2 q45 = __bfloat1622float2(*(__nv_bfloat162*)&qu.z);
                float2 q67 = __bfloat1622float2(*(__nv_bfloat162*)&qu.w);
                float r0 = fmaxf(v0.x + p01.x + q01.x + bi0.x, 0.f);
                float r1 = fmaxf(v0.y + p01.y + q01.y + bi0.y, 0.f);
                float r2 = fmaxf(v0.z + p23.x + q23.x + bi0.z, 0.f);
                float r3 = fmaxf(v0.w + p23.y + q23.y + bi0.w, 0.f);
                float r4 = fmaxf(v1.x + p45.x + q45.x + bi1.x, 0.f);
                float r5 = fmaxf(v1.y + p45.y + q45.y + bi1.y, 0.f);
                float r6 = fmaxf(v1.z + p67.x + q67.x + bi1.z, 0.f);
                float r7 = fmaxf(v1.w + p67.y + q67.y + bi1.w, 0.f);
                uint4 o;
                __nv_bfloat162 t;
                t = __floats2bfloat162_rn(r0, r1); o.x = *(uint32_t*)&t;
                t = __floats2bfloat162_rn(r2, r3); o.y = *(uint32_t*)&t;
                t = __floats2bfloat162_rn(r4, r5); o.z = *(uint32_t*)&t;
                t = __floats2bfloat162_rn(r6, r7); o.w = *(uint32_t*)&t;
                *(uint4*)(ch + e * LDA + jc) = o;
                __syncwarp();
            }
        }
        __syncthreads();  // ch complete; all warps done reading wB1
        if (c < 7) { stage_wb1(c + 1); CP_COMMIT(); }

        // ---- GEMM2: hacc += ch @ Wf1[jb:jb+128, :], 4 pipelined substages ----
        for (int ks = 0; ks < 4; ks++) {
            int stage = c * 4 + ks;
            if (ks == 0 && c < 7) { CP_WAIT1(); }  // allow wb1(c+1) in flight
            else { CP_WAIT0(); }
            __syncthreads();  // wB2(stage) ready; all warps done mma(stage-1)
            if (stage < 31) { stage_wb2(stage + 1); CP_COMMIT(); }
            const __nv_bfloat16* wB2p =
                (const __nv_bfloat16*)(sm + M4_WB2 + (stage & 1) * 33280);
#pragma unroll
            for (int k2 = 0; k2 < 2; k2++) {
                FragA a[4];
#pragma unroll
                for (int mt = 0; mt < 4; mt++)
                    wmma::load_matrix_sync(a[mt], ch + (mt * 16) * LDA + ks * 32 + k2 * 16, LDA);
#pragma unroll
                for (int nt = 0; nt < 4; nt++) {
                    FragB b;
                    wmma::load_matrix_sync(b, wB2p + (k2 * 16) * LDB2 + w * 64 + nt * 16, LDB2);
#pragma unroll
                    for (int mt = 0; mt < 4; mt++)
                        wmma::mma_sync(hacc[mt][nt], a[mt], b, hacc[mt][nt]);
                }
            }
        }
    }
    __syncthreads();

    // ---- epilogue ----
    float* myscr = scr + w * 256;
#pragma unroll
    for (int mt = 0; mt < 4; mt++) {
#pragma unroll
        for (int nt = 0; nt < 4; nt++) {
            wmma::store_matrix_sync(myscr, hacc[mt][nt], 16, wmma::mem_row_major);
            __syncwarp();
            int r = lane & 15, cc0 = (lane >> 4) * 8;
            int n0 = w * 64 + nt * 16 + cc0;
            float s = 0.f;
#pragma unroll
            for (int cc = 0; cc < 8; cc++) {
                float v = myscr[r * 16 + cc0 + cc];
                int n = n0 + cc;
                s += fmaxf(v + bf1s[n], 0.f) * wf2s[n];
            }
            atomicAdd(&partial[mt * 16 + r], s);
            __syncwarp();
        }
    }
    __syncthreads();
    if (tid < TE4) {
        float lg = partial[tid] + bf2[0];
        outp[e0 + tid] = 1.f / (1.f + expf(-lg));
    }
}

// ---------------- launch ----------------
extern "C" void kernel_launch(void* const* d_in, const int* in_sizes, int n_in,
                              void* d_out, int out_size) {
    const float* x = (const float*)d_in[0];
    const int* ei = (const int*)d_in[1];
    const float* local_emb = (const float*)d_in[2];
    const float* W1 = (const float*)d_in[3];
    const float* a_src1 = (const float*)d_in[4];
    const float* a_trg1 = (const float*)d_in[5];
    const float* b1 = (const float*)d_in[6];
    const float* W2 = (const float*)d_in[7];
    const float* a_src2 = (const float*)d_in[8];
    const float* a_trg2 = (const float*)d_in[9];
    const float* b2 = (const float*)d_in[10];
    const float* Wi = (const float*)d_in[11];
    const float* bi = (const float*)d_in[12];
    const float* Wf1 = (const float*)d_in[13];
    const float* bf1 = (const float*)d_in[14];
    const float* Wf2 = (const float*)d_in[15];
    const float* bf2 = (const float*)d_in[16];
    float* outp = (float*)d_out;

    void* tmp;
    float *p_proj1, *p_ssrc1, *p_strg1, *p_e1, *p_den1, *p_agg1, *p_h;
    float *p_proj2, *p_ssrc2, *p_strg2, *p_e2, *p_den2, *p_agg2, *p_out2;
    __nv_bfloat16 *p_out2h, *p_PQh, *p_wacad, *p_wibh, *p_wf1h;
#define SYM(p, s) cudaGetSymbolAddress(&tmp, s); p = (decltype(p))tmp;
    SYM(p_proj1, g_proj1) SYM(p_ssrc1, g_ssrc1) SYM(p_strg1, g_strg1)
    SYM(p_e1, g_e1) SYM(p_den1, g_den1) SYM(p_agg1, g_agg1) SYM(p_h, g_h)
    SYM(p_proj2, g_proj2) SYM(p_ssrc2, g_ssrc2) SYM(p_strg2, g_strg2)
    SYM(p_e2, g_e2) SYM(p_den2, g_den2) SYM(p_agg2, g_agg2) SYM(p_out2, g_out2)
    SYM(p_out2h, g_out2h) SYM(p_PQh, g_PQh) SYM(p_wacad, g_wacad)
    SYM(p_wibh, g_wib_h) SYM(p_wf1h, g_wf1_h)
#undef SYM

    const int EB = (EE + 255) / 256;
    cudaFuncSetAttribute(k_edge_mlp4, cudaFuncAttributeMaxDynamicSharedMemorySize, M4_TOTAL);
    cudaFuncSetAttribute(k_gemm_tf32<128, 256>,
                         cudaFuncAttributeMaxDynamicSharedMemorySize, TF32_SMEM);
    cudaFuncSetAttribute(k_gemm_tf32<512, 512>,
                         cudaFuncAttributeMaxDynamicSharedMemorySize, TF32_SMEM);

    k_init<<<256, 256>>>();
    k_wprep<<<1024, 256>>>(Wi, p_wacad, p_wibh);
    k_cvt_wf1<<<2048, 256>>>(Wf1, p_wf1h);

    // ---- GAT layer 1 ----
    k_gemm_tf32<128, 256><<<dim3(NP / 128, 2), 256, TF32_SMEM>>>(x, W1, p_proj1);
    k_scores<2><<<NN, 64>>>(p_proj1, a_src1, a_trg1, p_ssrc1, p_strg1);
    k_edge_softmax<2><<<EB, 256>>>(ei, p_ssrc1, p_strg1, p_e1, p_den1);
    k_edge_agg<2><<<EE / 8, 256>>>(ei, p_e1, p_den1, p_proj1, p_agg1);
    k_finalize1<<<NN, 512>>>(local_emb, b1, p_agg1, p_h);

    // ---- GAT layer 2 ----
    k_gemm_tf32<512, 512><<<dim3(NP / 128, 4), 256, TF32_SMEM>>>(p_h, W2, p_proj2);
    k_scores<4><<<NN, 128>>>(p_proj2, a_src2, a_trg2, p_ssrc2, p_strg2);
    k_edge_softmax<4><<<EB, 256>>>(ei, p_ssrc2, p_strg2, p_e2, p_den2);
    k_edge_agg<4><<<EE / 8, 256>>>(ei, p_e2, p_den2, p_proj2, p_agg2);
    k_finalize2<<<NN, 128>>>(b2, p_agg2, p_out2, p_out2h);

    // ---- P|Q combined bf16 GEMM ----
    k_gemm_bf16h<128, 2048><<<dim3(NP / 128, 16), 256>>>(p_out2h, p_wacad, p_PQh);

    // ---- fused edge MLP (pipelined bf16 wmma, per-warp elementwise) ----
    k_edge_mlp4<<<EE / TE4, 256, M4_TOTAL>>>(ei, p_out2, p_PQh, p_wibh, bi, p_wf1h,
                                             bf1, Wf2, bf2, outp);
}

// round 10
// speedup vs baseline: 5.6308x; 1.1674x over previous
#include <cuda_runtime.h>
#include <cuda_bf16.h>
#include <mma.h>
#include <math.h>
#include <cstdint>

using namespace nvcuda;

#define NN 10000
#define NP 10112
#define EE 160000

// ---------------- device scratch ----------------
__device__ float g_proj1[NP * 256];
__device__ float g_ssrc1[NN * 2];
__device__ float g_strg1[NN * 2];
__device__ float g_den1[NN * 2];
__device__ float g_agg1[NN * 256];
__device__ float g_h[NP * 512];
__device__ float g_proj2[NP * 512];
__device__ float g_ssrc2[NN * 4];
__device__ float g_strg2[NN * 4];
__device__ float g_den2[NN * 4];
__device__ float g_agg2[NN * 512];
__device__ __nv_bfloat16 g_out2h[NP * 128];
__device__ __nv_bfloat16 g_PQh[NP * 2048];        // bf16 [P | Q]
__device__ __nv_bfloat16 g_wacad[128 * 2048];     // [Wi_a+Wi_c | Wi_a+Wi_d] bf16
__device__ __nv_bfloat16 g_wib_h[128 * 1024];     // Wi rows 128..255, bf16
__device__ __nv_bfloat16 g_wf1_h[1024 * 512];     // Wf1 bf16
__device__ __nv_bfloat16 g_msh[EE * 128];         // e1*e2 bf16
__device__ __nv_bfloat16 g_fused[(size_t)EE * 1024];  // relu layer-1 activations
__device__ float g_logit[EE];

__device__ __forceinline__ float eluf(float v) { return v > 0.f ? v : expm1f(v); }

__device__ __forceinline__ void red4(float* p, float a, float b, float c, float d) {
    asm volatile("red.global.add.v4.f32 [%0], {%1,%2,%3,%4};"
                 :: "l"(p), "f"(a), "f"(b), "f"(c), "f"(d) : "memory");
}

__device__ __forceinline__ uint32_t smem_u32(const void* p) {
    uint32_t a;
    asm("{ .reg .u64 t; cvta.to.shared.u64 t, %1; cvt.u32.u64 %0, t; }" : "=r"(a) : "l"(p));
    return a;
}
__device__ __forceinline__ void cpa16(uint32_t saddr, const void* g) {
    asm volatile("cp.async.cg.shared.global [%0], [%1], 16;" :: "r"(saddr), "l"(g));
}
__device__ __forceinline__ void cpa16p(uint32_t saddr, const void* g, bool pred) {
    int sz = pred ? 16 : 0;
    asm volatile("cp.async.cg.shared.global [%0], [%1], 16, %2;"
                 :: "r"(saddr), "l"(g), "r"(sz));
}
#define CP_COMMIT() asm volatile("cp.async.commit_group;" ::: "memory")
#define CP_WAIT0()  asm volatile("cp.async.wait_group 0;" ::: "memory")
#define CP_WAIT1()  asm volatile("cp.async.wait_group 1;" ::: "memory")

// ---------------- init ----------------
__global__ void k_init() {
    int i = blockIdx.x * blockDim.x + threadIdx.x;
    int stride = gridDim.x * blockDim.x;
    for (int j = i; j < NN * 256; j += stride) g_agg1[j] = 0.f;
    for (int j = i; j < NN * 512; j += stride) g_agg2[j] = 0.f;
    for (int j = i; j < NN * 2; j += stride) g_den1[j] = 0.f;
    for (int j = i; j < NN * 4; j += stride) g_den2[j] = 0.f;
    for (int j = i; j < EE; j += stride) g_logit[j] = 0.f;
}

// =================== tf32 GEMM (cp.async double-buffered) ===================
template <int K, int COLS>
__global__ __launch_bounds__(256) void k_gemm_tf32(const float* __restrict__ A,
                                                   const float* __restrict__ W,
                                                   float* __restrict__ C) {
    constexpr int KC = 32;
    constexpr int NSTG = K / KC;
    extern __shared__ float smf[];
    float* As = smf;                   // [2][128][36]
    float* Ws = smf + 2 * 128 * 36;    // [2][32][132]
    uint32_t asb = smem_u32(As), wsb = smem_u32(Ws);
    int m0 = blockIdx.x * 128, n0 = blockIdx.y * 128;
    int tid = threadIdx.x, w = tid >> 5;
    int wm = w & 1, wn = w >> 1;

    auto stage = [&](int s) {
        int kc = s * KC, buf = s & 1;
#pragma unroll
        for (int i = tid; i < 1024; i += 256) {
            int r = i >> 3, c = (i & 7) * 4;
            int gm = m0 + r;
            const float* src = (gm < NN) ? (A + (size_t)gm * K + kc + c) : A;
            cpa16p(asb + (uint32_t)((buf * 128 + r) * 36 + c) * 4, src, gm < NN);
        }
#pragma unroll
        for (int i = tid; i < 1024; i += 256) {
            int r = i >> 5, c = (i & 31) * 4;
            cpa16(wsb + (uint32_t)((buf * 32 + r) * 132 + c) * 4,
                  W + (size_t)(kc + r) * COLS + n0 + c);
        }
    };

    wmma::fragment<wmma::accumulator, 16, 16, 8, float> acc[4][2];
#pragma unroll
    for (int mt = 0; mt < 4; mt++)
#pragma unroll
        for (int nt = 0; nt < 2; nt++) wmma::fill_fragment(acc[mt][nt], 0.f);

    stage(0); CP_COMMIT();
    for (int s = 0; s < NSTG; s++) {
        if (s + 1 < NSTG) { stage(s + 1); CP_COMMIT(); CP_WAIT1(); }
        else { CP_WAIT0(); }
        __syncthreads();
        const float* Ab = As + (s & 1) * 128 * 36;
        const float* Wb = Ws + (s & 1) * 32 * 132;
#pragma unroll
        for (int k8 = 0; k8 < KC / 8; k8++) {
            wmma::fragment<wmma::matrix_a, 16, 16, 8, wmma::precision::tf32,
                           wmma::row_major> a[4];
#pragma unroll
            for (int mt = 0; mt < 4; mt++)
                wmma::load_matrix_sync(a[mt], Ab + (wm * 64 + mt * 16) * 36 + k8 * 8, 36);
#pragma unroll
            for (int nt = 0; nt < 2; nt++) {
                wmma::fragment<wmma::matrix_b, 16, 16, 8, wmma::precision::tf32,
                               wmma::row_major> b;
                wmma::load_matrix_sync(b, Wb + (k8 * 8) * 132 + wn * 32 + nt * 16, 132);
#pragma unroll
                for (int mt = 0; mt < 4; mt++)
                    wmma::mma_sync(acc[mt][nt], a[mt], b, acc[mt][nt]);
            }
        }
        __syncthreads();
    }
#pragma unroll
    for (int mt = 0; mt < 4; mt++)
#pragma unroll
        for (int nt = 0; nt < 2; nt++) {
            int gm = m0 + wm * 64 + mt * 16;
            wmma::store_matrix_sync(C + (size_t)gm * COLS + n0 + wn * 32 + nt * 16,
                                    acc[mt][nt], COLS, wmma::mem_row_major);
        }
}
#define TF32_SMEM ((2 * 128 * 36 + 2 * 32 * 132) * 4)

// ====== bf16 GEMM (A bf16, W bf16, C bf16) — for P|Q ========================
template <int K, int COLS>
__global__ __launch_bounds__(256) void k_gemm_bf16h(const __nv_bfloat16* __restrict__ A,
                                                    const __nv_bfloat16* __restrict__ W,
                                                    __nv_bfloat16* __restrict__ C) {
    constexpr int KC = 32;
    constexpr int NSTG = K / KC;
    __shared__ __nv_bfloat16 As[2][128][40];
    __shared__ __nv_bfloat16 Ws[2][KC][136];
    uint32_t asb = smem_u32(&As[0][0][0]), wsb = smem_u32(&Ws[0][0][0]);
    int m0 = blockIdx.x * 128, n0 = blockIdx.y * 128;
    int tid = threadIdx.x, w = tid >> 5, lane = tid & 31;
    int wm = w & 1, wn = w >> 1;

    auto stage = [&](int s) {
        int kc = s * KC, buf = s & 1;
#pragma unroll
        for (int i = tid; i < 512; i += 256) {
            int r = i >> 2, c = (i & 3) * 8;
            cpa16(asb + (uint32_t)((buf * 128 + r) * 40 + c) * 2,
                  A + (size_t)(m0 + r) * K + kc + c);
        }
#pragma unroll
        for (int i = tid; i < 512; i += 256) {
            int r = i >> 4, c = (i & 15) * 8;
            cpa16(wsb + (uint32_t)((buf * KC + r) * 136 + c) * 2,
                  W + (size_t)(kc + r) * COLS + n0 + c);
        }
    };

    wmma::fragment<wmma::accumulator, 16, 16, 16, float> acc[4][2];
#pragma unroll
    for (int mt = 0; mt < 4; mt++)
#pragma unroll
        for (int nt = 0; nt < 2; nt++) wmma::fill_fragment(acc[mt][nt], 0.f);

    stage(0); CP_COMMIT();
    for (int s = 0; s < NSTG; s++) {
        if (s + 1 < NSTG) { stage(s + 1); CP_COMMIT(); CP_WAIT1(); }
        else { CP_WAIT0(); }
        __syncthreads();
        const __nv_bfloat16* Ab = &As[s & 1][0][0];
        const __nv_bfloat16* Wb = &Ws[s & 1][0][0];
#pragma unroll
        for (int k16 = 0; k16 < KC / 16; k16++) {
            wmma::fragment<wmma::matrix_a, 16, 16, 16, __nv_bfloat16, wmma::row_major> a[4];
#pragma unroll
            for (int mt = 0; mt < 4; mt++)
                wmma::load_matrix_sync(a[mt], Ab + (wm * 64 + mt * 16) * 40 + k16 * 16, 40);
#pragma unroll
            for (int nt = 0; nt < 2; nt++) {
                wmma::fragment<wmma::matrix_b, 16, 16, 16, __nv_bfloat16, wmma::row_major> b;
                wmma::load_matrix_sync(b, Wb + (k16 * 16) * 136 + wn * 32 + nt * 16, 136);
#pragma unroll
                for (int mt = 0; mt < 4; mt++)
                    wmma::mma_sync(acc[mt][nt], a[mt], b, acc[mt][nt]);
            }
        }
        __syncthreads();
    }
    float* scratch = (float*)(&As[0][0][0]) + w * 256;
#pragma unroll
    for (int mt = 0; mt < 4; mt++)
#pragma unroll
        for (int nt = 0; nt < 2; nt++) {
            wmma::store_matrix_sync(scratch, acc[mt][nt], 16, wmma::mem_row_major);
            __syncwarp();
            int row = lane >> 1, colb = (lane & 1) * 8;
            const float* sp = scratch + row * 16 + colb;
            int gm = m0 + wm * 64 + mt * 16 + row;
            __nv_bfloat16* dst = C + (size_t)gm * COLS + n0 + wn * 32 + nt * 16 + colb;
            uint4 o;
            __nv_bfloat162 t;
            t = __floats2bfloat162_rn(sp[0], sp[1]); o.x = *(uint32_t*)&t;
            t = __floats2bfloat162_rn(sp[2], sp[3]); o.y = *(uint32_t*)&t;
            t = __floats2bfloat162_rn(sp[4], sp[5]); o.z = *(uint32_t*)&t;
            t = __floats2bfloat162_rn(sp[6], sp[7]); o.w = *(uint32_t*)&t;
            *(uint4*)dst = o;
            __syncwarp();
        }
}

// ---------------- attention score projections ----------------
template <int H>
__global__ void k_scores(const float* __restrict__ proj, const float* __restrict__ asrc,
                         const float* __restrict__ atrg, float* __restrict__ ssrc,
                         float* __restrict__ strg) {
    int n = blockIdx.x;
    int h = threadIdx.x >> 5, lane = threadIdx.x & 31;
    float4 p = *(const float4*)(proj + ((size_t)n * H + h) * 128 + lane * 4);
    float4 a = *(const float4*)(asrc + h * 128 + lane * 4);
    float4 b = *(const float4*)(atrg + h * 128 + lane * 4);
    float ps = p.x * a.x + p.y * a.y + p.z * a.z + p.w * a.w;
    float pt = p.x * b.x + p.y * b.y + p.z * b.z + p.w * b.w;
#pragma unroll
    for (int o = 16; o > 0; o >>= 1) {
        ps += __shfl_down_sync(0xffffffffu, ps, o);
        pt += __shfl_down_sync(0xffffffffu, pt, o);
    }
    if (lane == 0) { ssrc[n * H + h] = ps; strg[n * H + h] = pt; }
}

// ---- merged edge pass: ex + denom + UNNORMALIZED aggregate (1 sweep) -------
// att = ex/den[t] is applied at finalize: agg holds sum(ex*proj), den holds sum(ex)
template <int H>
__global__ void k_edge_pass(const int* __restrict__ ei, const float* __restrict__ ss,
                            const float* __restrict__ st, const float* __restrict__ proj,
                            float* __restrict__ den, float* __restrict__ agg) {
    int g = blockIdx.x * blockDim.x + threadIdx.x;
    int i = g >> 5, lane = g & 31;
    if (i >= EE) return;
    int s = ei[i], t = ei[EE + i];
#pragma unroll
    for (int h = 0; h < H; h++) {
        float v = ss[s * H + h] + st[t * H + h];
        v = v > 0.f ? v : 0.2f * v;
        float ex = expf(v);
        if (lane == 0) atomicAdd(&den[t * H + h], ex);
        float4 p = *(const float4*)(proj + ((size_t)s * H + h) * 128 + lane * 4);
        float* d = agg + ((size_t)t * H + h) * 128 + lane * 4;
        red4(d, p.x * ex, p.y * ex, p.z * ex, p.w * ex);
    }
}

__global__ void k_finalize1(const float* __restrict__ local_emb, const float* __restrict__ b1,
                            const float* __restrict__ agg, const float* __restrict__ den,
                            float* __restrict__ hbuf) {
    int n = blockIdx.x, c = threadIdx.x;
    int h = c >> 8, j = c & 255;
    float v = (j < 128) ? agg[(size_t)n * 256 + h * 128 + j] / (den[n * 2 + h] + 1e-16f)
                        : local_emb[(size_t)n * 128 + (j - 128)];
    v += b1[c];
    hbuf[(size_t)n * 512 + c] = eluf(v);
}

__global__ void k_finalize2(const float* __restrict__ b2, const float* __restrict__ agg,
                            const float* __restrict__ den,
                            __nv_bfloat16* __restrict__ out2h) {
    int n = blockIdx.x, f = threadIdx.x;
    const float* a = agg + (size_t)n * 512;
    float v = 0.f;
#pragma unroll
    for (int h = 0; h < 4; h++) v += a[h * 128 + f] / (den[n * 4 + h] + 1e-16f);
    v = eluf(0.25f * v + b2[f]);
    out2h[(size_t)n * 128 + f] = __float2bfloat16(v);
}

// ---------------- MLP weight prep ----------------
__global__ void k_wprep(const float* __restrict__ Wi, __nv_bfloat16* __restrict__ wacad,
                        __nv_bfloat16* __restrict__ wibh) {
    int i = blockIdx.x * blockDim.x + threadIdx.x;
    if (i >= 128 * 2048) return;
    int k = i >> 11, j = i & 2047;
    float v;
    if (j < 1024)
        v = Wi[(size_t)k * 1024 + j] + Wi[(size_t)(256 + k) * 1024 + j];
    else
        v = Wi[(size_t)k * 1024 + (j - 1024)] + Wi[(size_t)(384 + k) * 1024 + (j - 1024)];
    wacad[i] = __float2bfloat16(v);
    if (j < 1024) wibh[(size_t)k * 1024 + j] = __float2bfloat16(Wi[(size_t)(128 + k) * 1024 + j]);
}

__global__ void k_cvt_wf1(const float* __restrict__ Wf1, __nv_bfloat16* __restrict__ out) {
    int i = blockIdx.x * blockDim.x + threadIdx.x;
    if (i < 1024 * 512) out[i] = __float2bfloat16(Wf1[i]);
}

// ---------------- msh = bf16(e1 * e2) ----------------
__global__ void k_msh(const int* __restrict__ ei, const __nv_bfloat16* __restrict__ out2h,
                      __nv_bfloat16* __restrict__ msh) {
    int g = blockIdx.x * blockDim.x + threadIdx.x;
    int e = g >> 5, lane = g & 31;
    if (e >= EE) return;
    int s = ei[e], t = ei[EE + e];
    uint2 au = *(const uint2*)(out2h + (size_t)s * 128 + lane * 4);
    uint2 bu = *(const uint2*)(out2h + (size_t)t * 128 + lane * 4);
    float2 a01 = __bfloat1622float2(*(__nv_bfloat162*)&au.x);
    float2 a23 = __bfloat1622float2(*(__nv_bfloat162*)&au.y);
    float2 b01 = __bfloat1622float2(*(__nv_bfloat162*)&bu.x);
    float2 b23 = __bfloat1622float2(*(__nv_bfloat162*)&bu.y);
    uint2 o;
    __nv_bfloat162 t2;
    t2 = __floats2bfloat162_rn(a01.x * b01.x, a01.y * b01.y); o.x = *(uint32_t*)&t2;
    t2 = __floats2bfloat162_rn(a23.x * b23.x, a23.y * b23.y); o.y = *(uint32_t*)&t2;
    *(uint2*)(msh + (size_t)e * 128 + lane * 4) = o;
}

// ===== k_fused: fused[e, n0:n0+128] = relu(msh@Wib + P[s] + Q[t] + bi) =======
// grid (EE/128, 8). Dense GEMM K=128, occupancy 2.
#define F_AS 0            // 128x136 bf16 (34816)
#define F_BS 34816        // 128x136 bf16 (34816)
#define F_SCR 69632       // 8x256 f32 (8192)
#define F_SIDX 77824      // 128 int
#define F_TIDX 78336      // 128 int
#define F_TOTAL 78848

typedef wmma::fragment<wmma::matrix_a, 16, 16, 16, __nv_bfloat16, wmma::row_major> FragA;
typedef wmma::fragment<wmma::matrix_b, 16, 16, 16, __nv_bfloat16, wmma::row_major> FragB;
typedef wmma::fragment<wmma::accumulator, 16, 16, 16, float> FragC;

__global__ __launch_bounds__(256, 2) void k_fused(
    const int* __restrict__ ei, const __nv_bfloat16* __restrict__ msh,
    const __nv_bfloat16* __restrict__ WibH, const __nv_bfloat16* __restrict__ PQh,
    const float* __restrict__ bi, __nv_bfloat16* __restrict__ fused) {
    extern __shared__ char sm[];
    __nv_bfloat16* As = (__nv_bfloat16*)(sm + F_AS);
    __nv_bfloat16* Bs = (__nv_bfloat16*)(sm + F_BS);
    float* scr = (float*)(sm + F_SCR);
    int* sidx = (int*)(sm + F_SIDX);
    int* tidx = (int*)(sm + F_TIDX);
    uint32_t smb = smem_u32(sm);

    int tid = threadIdx.x, w = tid >> 5, lane = tid & 31;
    int e0 = blockIdx.x * 128, n0 = blockIdx.y * 128;
    int wm = w & 3, wn = w >> 2;

    if (tid < 128) sidx[tid] = ei[e0 + tid];
    else tidx[tid - 128] = ei[EE + e0 + tid - 128];

    // stage A (msh rows) and B (Wib cols) via cp.async, one shot
#pragma unroll
    for (int i = tid; i < 2048; i += 256) {
        int r = i >> 4, c = (i & 15) * 8;
        cpa16(smb + F_AS + (uint32_t)(r * 136 + c) * 2, msh + (size_t)(e0 + r) * 128 + c);
    }
#pragma unroll
    for (int i = tid; i < 2048; i += 256) {
        int r = i >> 4, c = (i & 15) * 8;
        cpa16(smb + F_BS + (uint32_t)(r * 136 + c) * 2, WibH + (size_t)r * 1024 + n0 + c);
    }
    CP_COMMIT(); CP_WAIT0();
    __syncthreads();

    FragC acc[2][4];
#pragma unroll
    for (int mt = 0; mt < 2; mt++)
#pragma unroll
        for (int nt = 0; nt < 4; nt++) wmma::fill_fragment(acc[mt][nt], 0.f);
#pragma unroll
    for (int k16 = 0; k16 < 8; k16++) {
        FragA a[2];
#pragma unroll
        for (int mt = 0; mt < 2; mt++)
            wmma::load_matrix_sync(a[mt], As + (wm * 32 + mt * 16) * 136 + k16 * 16, 136);
#pragma unroll
        for (int nt = 0; nt < 4; nt++) {
            FragB b;
            wmma::load_matrix_sync(b, Bs + (k16 * 16) * 136 + wn * 64 + nt * 16, 136);
#pragma unroll
            for (int mt = 0; mt < 2; mt++)
                wmma::mma_sync(acc[mt][nt], a[mt], b, acc[mt][nt]);
        }
    }

    // epilogue: + P[s] + Q[t] + bi, relu, write fused (bf16)
    float* wscr = scr + w * 256;
    int r = lane >> 1, cb = (lane & 1) * 8;
#pragma unroll
    for (int mt = 0; mt < 2; mt++) {
#pragma unroll
        for (int nt = 0; nt < 4; nt++) {
            wmma::store_matrix_sync(wscr, acc[mt][nt], 16, wmma::mem_row_major);
            __syncwarp();
            int e = wm * 32 + mt * 16 + r;
            int jc = n0 + wn * 64 + nt * 16 + cb;  // global col 0..1023
            float4 v0 = *(float4*)(wscr + r * 16 + cb);
            float4 v1 = *(float4*)(wscr + r * 16 + cb + 4);
            uint4 pu = *(const uint4*)(PQh + (size_t)sidx[e] * 2048 + jc);
            uint4 qu = *(const uint4*)(PQh + (size_t)tidx[e] * 2048 + 1024 + jc);
            float4 bi0 = *(const float4*)(bi + jc);
            float4 bi1 = *(const float4*)(bi + jc + 4);
            float2 p01 = __bfloat1622float2(*(__nv_bfloat162*)&pu.x);
            float2 p23 = __bfloat1622float2(*(__nv_bfloat162*)&pu.y);
            float2 p45 = __bfloat1622float2(*(__nv_bfloat162*)&pu.z);
            float2 p67 = __bfloat1622float2(*(__nv_bfloat162*)&pu.w);
            float2 q01 = __bfloat1622float2(*(__nv_bfloat162*)&qu.x);
            float2 q23 = __bfloat1622float2(*(__nv_bfloat162*)&qu.y);
            float2 q45 = __bfloat1622float2(*(__nv_bfloat162*)&qu.z);
            float2 q67 = __bfloat1622float2(*(__nv_bfloat162*)&qu.w);
            float r0 = fmaxf(v0.x + p01.x + q01.x + bi0.x, 0.f);
            float r1 = fmaxf(v0.y + p01.y + q01.y + bi0.y, 0.f);
            float r2 = fmaxf(v0.z + p23.x + q23.x + bi0.z, 0.f);
            float r3 = fmaxf(v0.w + p23.y + q23.y + bi0.w, 0.f);
            float r4 = fmaxf(v1.x + p45.x + q45.x + bi1.x, 0.f);
            float r5 = fmaxf(v1.y + p45.y + q45.y + bi1.y, 0.f);
            float r6 = fmaxf(v1.z + p67.x + q67.x + bi1.z, 0.f);
            float r7 = fmaxf(v1.w + p67.y + q67.y + bi1.w, 0.f);
            uint4 o;
            __nv_bfloat162 t2;
            t2 = __floats2bfloat162_rn(r0, r1); o.x = *(uint32_t*)&t2;
            t2 = __floats2bfloat162_rn(r2, r3); o.y = *(uint32_t*)&t2;
            t2 = __floats2bfloat162_rn(r4, r5); o.z = *(uint32_t*)&t2;
            t2 = __floats2bfloat162_rn(r6, r7); o.w = *(uint32_t*)&t2;
            *(uint4*)(fused + (size_t)(e0 + e) * 1024 + jc) = o;
            __syncwarp();
        }
    }
}

// ===== k_hdn: logits += sum_n relu(fused@Wf1 + bf1) * Wf2 (n-split exact) ====
// grid (EE/128, 4). Dense GEMM K=1024, double-buffered, occupancy 2.
#define H_AS 0            // 2 x 128x72 bf16 (36864)
#define H_BS 36864        // 2 x 64x136 bf16 (34816)
#define H_TOTAL 71680

__global__ __launch_bounds__(256, 2) void k_hdn(
    const __nv_bfloat16* __restrict__ fused, const __nv_bfloat16* __restrict__ Wf1H,
    const float* __restrict__ bf1, const float* __restrict__ Wf2,
    float* __restrict__ logit) {
    extern __shared__ char sm[];
    uint32_t smb = smem_u32(sm);
    __nv_bfloat16* As = (__nv_bfloat16*)(sm + H_AS);
    __nv_bfloat16* Bs = (__nv_bfloat16*)(sm + H_BS);

    int tid = threadIdx.x, w = tid >> 5, lane = tid & 31;
    int e0 = blockIdx.x * 128, n0 = blockIdx.y * 128;
    int wm = w & 3, wn = w >> 2;

    auto stage = [&](int s) {
        int kc = s * 64, buf = s & 1;
#pragma unroll
        for (int i = tid; i < 1024; i += 256) {
            int r = i >> 3, c = (i & 7) * 8;
            cpa16(smb + H_AS + (uint32_t)((buf * 128 + r) * 72 + c) * 2,
                  fused + (size_t)(e0 + r) * 1024 + kc + c);
        }
#pragma unroll
        for (int i = tid; i < 1024; i += 256) {
            int r = i >> 4, c = (i & 15) * 8;
            cpa16(smb + H_BS + (uint32_t)((buf * 64 + r) * 136 + c) * 2,
                  Wf1H + (size_t)(kc + r) * 512 + n0 + c);
        }
    };

    FragC acc[2][4];
#pragma unroll
    for (int mt = 0; mt < 2; mt++)
#pragma unroll
        for (int nt = 0; nt < 4; nt++) wmma::fill_fragment(acc[mt][nt], 0.f);

    stage(0); CP_COMMIT();
    for (int s = 0; s < 16; s++) {
        if (s + 1 < 16) { stage(s + 1); CP_COMMIT(); CP_WAIT1(); }
        else { CP_WAIT0(); }
        __syncthreads();
        const __nv_bfloat16* Ab = As + (s & 1) * 128 * 72;
        const __nv_bfloat16* Bb = Bs + (s & 1) * 64 * 136;
#pragma unroll
        for (int k16 = 0; k16 < 4; k16++) {
            FragA a[2];
#pragma unroll
            for (int mt = 0; mt < 2; mt++)
                wmma::load_matrix_sync(a[mt], Ab + (wm * 32 + mt * 16) * 72 + k16 * 16, 72);
#pragma unroll
            for (int nt = 0; nt < 4; nt++) {
                FragB b;
                wmma::load_matrix_sync(b, Bb + (k16 * 16) * 136 + wn * 64 + nt * 16, 136);
#pragma unroll
                for (int mt = 0; mt < 2; mt++)
                    wmma::mma_sync(acc[mt][nt], a[mt], b, acc[mt][nt]);
            }
        }
        __syncthreads();
    }

    // epilogue: relu(+bf1) * Wf2 partial sums -> atomicAdd logits
    float* wscr = (float*)(sm + H_AS) + w * 256;  // As free after final sync
    int r = lane >> 1, cb = (lane & 1) * 8;
#pragma unroll
    for (int mt = 0; mt < 2; mt++) {
        float part = 0.f;
#pragma unroll
        for (int nt = 0; nt < 4; nt++) {
            wmma::store_matrix_sync(wscr, acc[mt][nt], 16, wmma::mem_row_major);
            __syncwarp();
            int ncol = n0 + wn * 64 + nt * 16 + cb;
            float4 v0 = *(float4*)(wscr + r * 16 + cb);
            float4 v1 = *(float4*)(wscr + r * 16 + cb + 4);
            float4 b0 = *(const float4*)(bf1 + ncol);
            float4 b1 = *(const float4*)(bf1 + ncol + 4);
            float4 w0 = *(const float4*)(Wf2 + ncol);
            float4 w1 = *(const float4*)(Wf2 + ncol + 4);
            part += fmaxf(v0.x + b0.x, 0.f) * w0.x + fmaxf(v0.y + b0.y, 0.f) * w0.y +
                    fmaxf(v0.z + b0.z, 0.f) * w0.z + fmaxf(v0.w + b0.w, 0.f) * w0.w +
                    fmaxf(v1.x + b1.x, 0.f) * w1.x + fmaxf(v1.y + b1.y, 0.f) * w1.y +
                    fmaxf(v1.z + b1.z, 0.f) * w1.z + fmaxf(v1.w + b1.w, 0.f) * w1.w;
            __syncwarp();
        }
        part += __shfl_xor_sync(0xffffffffu, part, 1);
        if ((lane & 1) == 0)
            atomicAdd(&logit[e0 + wm * 32 + mt * 16 + r], part);
    }
}

// ---------------- sigmoid ----------------
__global__ void k_sigmoid(const float* __restrict__ logit, const float* __restrict__ bf2,
                          float* __restrict__ outp) {
    int i = blockIdx.x * blockDim.x + threadIdx.x;
    if (i < EE) outp[i] = 1.f / (1.f + expf(-(logit[i] + bf2[0])));
}

// ---------------- launch ----------------
extern "C" void kernel_launch(void* const* d_in, const int* in_sizes, int n_in,
                              void* d_out, int out_size) {
    const float* x = (const float*)d_in[0];
    const int* ei = (const int*)d_in[1];
    const float* local_emb = (const float*)d_in[2];
    const float* W1 = (const float*)d_in[3];
    const float* a_src1 = (const float*)d_in[4];
    const float* a_trg1 = (const float*)d_in[5];
    const float* b1 = (const float*)d_in[6];
    const float* W2 = (const float*)d_in[7];
    const float* a_src2 = (const float*)d_in[8];
    const float* a_trg2 = (const float*)d_in[9];
    const float* b2 = (const float*)d_in[10];
    const float* Wi = (const float*)d_in[11];
    const float* bi = (const float*)d_in[12];
    const float* Wf1 = (const float*)d_in[13];
    const float* bf1 = (const float*)d_in[14];
    const float* Wf2 = (const float*)d_in[15];
    const float* bf2 = (const float*)d_in[16];
    float* outp = (float*)d_out;

    void* tmp;
    float *p_proj1, *p_ssrc1, *p_strg1, *p_den1, *p_agg1, *p_h;
    float *p_proj2, *p_ssrc2, *p_strg2, *p_den2, *p_agg2, *p_logit;
    __nv_bfloat16 *p_out2h, *p_PQh, *p_wacad, *p_wibh, *p_wf1h, *p_msh, *p_fused;
#define SYM(p, s) cudaGetSymbolAddress(&tmp, s); p = (decltype(p))tmp;
    SYM(p_proj1, g_proj1) SYM(p_ssrc1, g_ssrc1) SYM(p_strg1, g_strg1)
    SYM(p_den1, g_den1) SYM(p_agg1, g_agg1) SYM(p_h, g_h)
    SYM(p_proj2, g_proj2) SYM(p_ssrc2, g_ssrc2) SYM(p_strg2, g_strg2)
    SYM(p_den2, g_den2) SYM(p_agg2, g_agg2) SYM(p_logit, g_logit)
    SYM(p_out2h, g_out2h) SYM(p_PQh, g_PQh) SYM(p_wacad, g_wacad)
    SYM(p_wibh, g_wib_h) SYM(p_wf1h, g_wf1_h) SYM(p_msh, g_msh) SYM(p_fused, g_fused)
#undef SYM

    cudaFuncSetAttribute(k_gemm_tf32<128, 256>,
                         cudaFuncAttributeMaxDynamicSharedMemorySize, TF32_SMEM);
    cudaFuncSetAttribute(k_gemm_tf32<512, 512>,
                         cudaFuncAttributeMaxDynamicSharedMemorySize, TF32_SMEM);
    cudaFuncSetAttribute(k_fused, cudaFuncAttributeMaxDynamicSharedMemorySize, F_TOTAL);
    cudaFuncSetAttribute(k_hdn, cudaFuncAttributeMaxDynamicSharedMemorySize, H_TOTAL);

    k_init<<<256, 256>>>();
    k_wprep<<<1024, 256>>>(Wi, p_wacad, p_wibh);
    k_cvt_wf1<<<2048, 256>>>(Wf1, p_wf1h);

    // ---- GAT layer 1 ----
    k_gemm_tf32<128, 256><<<dim3(NP / 128, 2), 256, TF32_SMEM>>>(x, W1, p_proj1);
    k_scores<2><<<NN, 64>>>(p_proj1, a_src1, a_trg1, p_ssrc1, p_strg1);
    k_edge_pass<2><<<EE / 8, 256>>>(ei, p_ssrc1, p_strg1, p_proj1, p_den1, p_agg1);
    k_finalize1<<<NN, 512>>>(local_emb, b1, p_agg1, p_den1, p_h);

    // ---- GAT layer 2 ----
    k_gemm_tf32<512, 512><<<dim3(NP / 128, 4), 256, TF32_SMEM>>>(p_h, W2, p_proj2);
    k_scores<4><<<NN, 128>>>(p_proj2, a_src2, a_trg2, p_ssrc2, p_strg2);
    k_edge_pass<4><<<EE / 8, 256>>>(ei, p_ssrc2, p_strg2, p_proj2, p_den2, p_agg2);
    k_finalize2<<<NN, 128>>>(b2, p_agg2, p_den2, p_out2h);

    // ---- P|Q combined bf16 GEMM ----
    k_gemm_bf16h<128, 2048><<<dim3(NP / 128, 16), 256>>>(p_out2h, p_wacad, p_PQh);

    // ---- edge MLP as dense GEMMs ----
    k_msh<<<EE / 8, 256>>>(ei, p_out2h, p_msh);
    k_fused<<<dim3(EE / 128, 8), 256, F_TOTAL>>>(ei, p_msh, p_wibh, p_PQh, bi, p_fused);
    k_hdn<<<dim3(EE / 128, 4), 256, H_TOTAL>>>(p_fused, p_wf1h, bf1, Wf2, p_logit);
    k_sigmoid<<<(EE + 255) / 256, 256>>>(p_logit, bf2, outp);
}